// round 14
// baseline (speedup 1.0000x reference)
#include <cuda_runtime.h>
#include <cuda_bf16.h>
#include <cuda_fp16.h>
#include <math.h>
#include <stdint.h>

#define B_  4
#define H_  16
#define NT  512
#define NL  512
#define E_  64
#define P_  1024
#define BH  (B_*H_)
#define PRIOR 8.0f

typedef unsigned int u32;

// ---------------- scratch (device globals) ----------------
__device__ __nv_bfloat16 g_Uh[(size_t)B_*8192*P_];  // U split hi  [b*8192+m][p]
__device__ __nv_bfloat16 g_Ul[(size_t)B_*8192*P_];
__device__ __nv_bfloat16 g_rh[B_*NL*P_];            // r = mu/bv hi [b][n][p]
__device__ __nv_bfloat16 g_rl[B_*NL*P_];
__device__ __half        g_tf[B_*P_*NL];            // c1^T fp16 [b][p][n]
__device__ __half        g_Sf[(size_t)BH*NT*NL];    // attn fp16 [bh*Nt+m][n]
__device__ __nv_bfloat16 g_Wh[H_*E_*P_];            // w_v split hi [h*E+e][p]
__device__ __nv_bfloat16 g_Wl[H_*E_*P_];
__device__ __nv_bfloat16 g_Gh[(size_t)BH*NT*P_];    // G split hi [bh*Nt+m][p]
__device__ __nv_bfloat16 g_Gl[(size_t)BH*NT*P_];
__device__ __half        g_Df[(size_t)BH*E_*NL];    // D^T fp16 [bh][e][n]
__device__ float g_add[BH*NL];

// ---------------- helpers ----------------
__device__ __forceinline__ u32 s2u(const void* p) {
    u32 a; asm("{ .reg .u64 t; cvta.to.shared.u64 t, %1; cvt.u32.u64 %0, t; }" : "=r"(a) : "l"(p));
    return a;
}
__device__ __forceinline__ void ldsm4(u32& r0, u32& r1, u32& r2, u32& r3, u32 a) {
    asm volatile("ldmatrix.sync.aligned.m8n8.x4.shared.b16 {%0,%1,%2,%3}, [%4];"
        : "=r"(r0), "=r"(r1), "=r"(r2), "=r"(r3) : "r"(a));
}
__device__ __forceinline__ void mma_bf16(float* c, const u32* a, const u32* b) {
    asm volatile("mma.sync.aligned.m16n8k16.row.col.f32.bf16.bf16.f32 "
        "{%0,%1,%2,%3}, {%4,%5,%6,%7}, {%8,%9}, {%0,%1,%2,%3};"
        : "+f"(c[0]), "+f"(c[1]), "+f"(c[2]), "+f"(c[3])
        : "r"(a[0]), "r"(a[1]), "r"(a[2]), "r"(a[3]), "r"(b[0]), "r"(b[1]));
}
__device__ __forceinline__ void mma_f16(float* c, const u32* a, const u32* b) {
    asm volatile("mma.sync.aligned.m16n8k16.row.col.f32.f16.f16.f32 "
        "{%0,%1,%2,%3}, {%4,%5,%6,%7}, {%8,%9}, {%0,%1,%2,%3};"
        : "+f"(c[0]), "+f"(c[1]), "+f"(c[2]), "+f"(c[3])
        : "r"(a[0]), "r"(a[1]), "r"(a[2]), "r"(a[3]), "r"(b[0]), "r"(b[1]));
}
__device__ __forceinline__ void splitbf(float x, __nv_bfloat16& h, __nv_bfloat16& l) {
    h = __float2bfloat16_rn(x);
    l = __float2bfloat16_rn(x - __bfloat162float(h));
}
#define CPA(s, g)   asm volatile("cp.async.cg.shared.global [%0], [%1], 16;" :: "r"(s), "l"(g) : "memory")
#define CP_COMMIT() asm volatile("cp.async.commit_group;" ::: "memory")
#define CP_WAIT(n)  asm volatile("cp.async.wait_group %0;" :: "n"(n) : "memory")

#define SAS     72                   // padded smem stride (elems)
#define TILE_E  (128*SAS)            // elems per 128-row tile
#define TILE_B  (TILE_E*2)           // bytes
#define HTILE_E (64*SAS)
#define HTILE_B (HTILE_E*2)

// ---------------- K0: per-(b,n) precompute + splits + reductions ----------------
__global__ __launch_bounds__(256) void k_prep(
    const float* __restrict__ mu, const float* __restrict__ logvar,
    const float* __restrict__ pi, const unsigned char* __restrict__ mask)
{
    int n = blockIdx.x, b = blockIdx.y;
    int base = (b*NL + n)*P_;
    int t = threadIdx.x;
    float s2 = 0.f, s3 = 0.f;
#pragma unroll
    for (int i = 0; i < 4; i++) {
        int p = t + i*256;
        float m  = mu[base+p];
        float v  = expf(logvar[base+p]);
        float bv = v + PRIOR;
        float inv = 1.0f / bv;
        float r  = m * inv;
        float c1 = v * inv;
        __nv_bfloat16 h, l;
        splitbf(r, h, l);
        g_rh[base+p] = h; g_rl[base+p] = l;
        g_tf[((size_t)b*P_ + p)*NL + n] = __float2half_rn(c1);
        s2 += m * m * inv;
        s3 += logf(bv);
    }
    __shared__ float red2[8], red3[8];
#pragma unroll
    for (int o = 16; o > 0; o >>= 1) {
        s2 += __shfl_down_sync(0xffffffffu, s2, o);
        s3 += __shfl_down_sync(0xffffffffu, s3, o);
    }
    if ((t & 31) == 0) { red2[t>>5] = s2; red3[t>>5] = s3; }
    __syncthreads();
    __shared__ float sbase;
    if (t == 0) {
        float a2 = 0.f, a3 = 0.f;
        for (int i = 0; i < 8; i++) { a2 += red2[i]; a3 += red3[i]; }
        float piv = pi[b*NL + n];
        float pc  = fmaxf(piv, 1.17549435e-38f);
        sbase = logf(pc) - 0.5f*a2 - 0.5f*a3;
    }
    __syncthreads();
    if (t < H_) {
        float piv = pi[b*NL + n];
        bool msk = (mask[(b*H_ + t)*NL + n] != 0) || (piv <= 0.f);
        g_add[(b*H_ + t)*NL + n] = msk ? -INFINITY : sbase;
    }
}

// ---------------- generic fp32 -> bf16 hi/lo splitter ----------------
__global__ __launch_bounds__(256) void k_split(
    const float* __restrict__ X, __nv_bfloat16* __restrict__ Xh,
    __nv_bfloat16* __restrict__ Xl)
{
    size_t i = ((size_t)blockIdx.x * 256 + threadIdx.x) * 4;
    float4 v = *(const float4*)(X + i);
    __nv_bfloat16 h[4], l[4];
    splitbf(v.x, h[0], l[0]); splitbf(v.y, h[1], l[1]);
    splitbf(v.z, h[2], l[2]); splitbf(v.w, h[3], l[3]);
    uint2 uh, ul;
    uh.x = ((u32)__bfloat16_as_ushort(h[1]) << 16) | __bfloat16_as_ushort(h[0]);
    uh.y = ((u32)__bfloat16_as_ushort(h[3]) << 16) | __bfloat16_as_ushort(h[2]);
    ul.x = ((u32)__bfloat16_as_ushort(l[1]) << 16) | __bfloat16_as_ushort(l[0]);
    ul.y = ((u32)__bfloat16_as_ushort(l[3]) << 16) | __bfloat16_as_ushort(l[2]);
    *(uint2*)&Xh[i] = uh;
    *(uint2*)&Xl[i] = ul;
}

// ---------------- K_D: D^T = 8*(r @ w_v^T) + b_v^T, bf16 mma, 512t, dbuf -------
// tile 128(n) x 64(e); 16 warps in 8x2 (M=16, N=32 per warp)
__global__ __launch_bounds__(512, 1) void k_D_mma(const float* __restrict__ bvv)
{
    extern __shared__ char smraw[];
    u32 uSm = s2u(smraw);
    int t = threadIdx.x, lane = t & 31, wid = t >> 5;
    int wm = wid >> 1, wn = wid & 1;
    int bh = blockIdx.y, b = bh >> 4, h = bh & 15;
    int m0 = blockIdx.x * 128;                   // n-tile

    const __nv_bfloat16* Ah = g_rh + ((size_t)b*NL + m0)*P_;
    const __nv_bfloat16* Al = g_rl + ((size_t)b*NL + m0)*P_;
    const __nv_bfloat16* WhP = g_Wh + (size_t)h*E_*P_;
    const __nv_bfloat16* WlP = g_Wl + (size_t)h*E_*P_;
    const u32 BUFB = 2*TILE_B + 2*HTILE_B;

    int arow  = wm*16 + (lane & 15);
    int acolo = (lane >> 4) * 8;
    int brow  = wn*32 + (lane & 7) + ((lane >> 4) * 8);
    int bcolo = ((lane >> 3) & 1) * 8;

    float acc[4][4] = {};

    auto load_chunk = [&](int c, int buf) {
        u32 sbb = uSm + (u32)buf * BUFB;
        int k0 = c * 64;
#pragma unroll
        for (int i = 0; i < 2; i++) {                 // A tiles: 128 rows
            int q = t + i*512;
            int row = q >> 3, cc = (q & 7) * 8;
            u32 doff = (u32)(row*SAS + cc) * 2;
            size_t so = (size_t)row * P_ + k0 + cc;
            CPA(sbb + 0*TILE_B + doff, Ah + so);
            CPA(sbb + 1*TILE_B + doff, Al + so);
        }
        {                                             // W tiles: 64 rows
            int row = t >> 3, cc = (t & 7) * 8;
            u32 doff = (u32)(row*SAS + cc) * 2;
            size_t so = (size_t)row * P_ + k0 + cc;
            CPA(sbb + 2*TILE_B + doff, WhP + so);
            CPA(sbb + 2*TILE_B + HTILE_B + doff, WlP + so);
        }
    };

    load_chunk(0, 0); CP_COMMIT();
    for (int c = 0; c < 16; c++) {
        if (c < 15) { load_chunk(c+1, (c+1)&1); CP_COMMIT(); CP_WAIT(1); }
        else        { CP_WAIT(0); }
        __syncthreads();
        u32 u0 = uSm + (u32)(c&1) * BUFB;
        u32 uAh = u0, uAl = u0 + TILE_B, uWh = u0 + 2*TILE_B, uWl = uWh + HTILE_B;
#pragma unroll
        for (int ks = 0; ks < 4; ks++) {
            int k = ks * 16;
            u32 aH[4], aL[4], bH[4][2], bL[4][2];
            {
                u32 off = (u32)((arow*SAS + k + acolo) * 2);
                ldsm4(aH[0], aH[1], aH[2], aH[3], uAh + off);
                ldsm4(aL[0], aL[1], aL[2], aL[3], uAl + off);
            }
#pragma unroll
            for (int pr = 0; pr < 2; pr++) {
                u32 off = (u32)(((brow + pr*16)*SAS + k + bcolo) * 2);
                ldsm4(bH[2*pr][0], bH[2*pr][1], bH[2*pr+1][0], bH[2*pr+1][1], uWh + off);
                ldsm4(bL[2*pr][0], bL[2*pr][1], bL[2*pr+1][0], bL[2*pr+1][1], uWl + off);
            }
#pragma unroll
            for (int nt = 0; nt < 4; nt++) {
                mma_bf16(acc[nt], aH, bH[nt]);
                mma_bf16(acc[nt], aH, bL[nt]);
                mma_bf16(acc[nt], aL, bH[nt]);
            }
        }
        __syncthreads();
    }

    // epilogue: *8 + b_v^T, transposed fp16 scatter to g_Df[e][n]
    int r = lane >> 2, c2_ = (lane & 3) * 2;
    int gm0 = m0 + wm*16 + r;
    int gm1 = gm0 + 8;
#pragma unroll
    for (int nt = 0; nt < 4; nt++) {
        int ge = wn*32 + nt*8 + c2_;
        size_t be0 = ((size_t)h*E_ + ge)*NL;
        size_t be1 = be0 + NL;
        size_t de0 = ((size_t)bh*E_ + ge)*NL;
        size_t de1 = de0 + NL;
        g_Df[de0 + gm0] = __float2half_rn(PRIOR*acc[nt][0] + bvv[be0 + gm0]);
        g_Df[de1 + gm0] = __float2half_rn(PRIOR*acc[nt][1] + bvv[be1 + gm0]);
        g_Df[de0 + gm1] = __float2half_rn(PRIOR*acc[nt][2] + bvv[be0 + gm1]);
        g_Df[de1 + gm1] = __float2half_rn(PRIOR*acc[nt][3] + bvv[be1 + gm1]);
    }
}

// ---------------- K1: scores, bf16 3-product, 512t, dbuf ----------------
// tile 128(M) x 128(N); 16 warps in 4x4 (M=32, N=32 per warp)
__global__ __launch_bounds__(512, 1) void k_scores_mma(
    const float* __restrict__ pb, float* __restrict__ S)
{
    extern __shared__ char smraw[];
    u32 uSm = s2u(smraw);
    int t = threadIdx.x, lane = t & 31, wid = t >> 5;
    int wm = wid >> 2, wn = wid & 3;
    int n0 = blockIdx.x * 128, m0 = blockIdx.y * 128, b = blockIdx.z;

    const __nv_bfloat16* Ah = g_Uh + ((size_t)b*8192 + m0)*P_;
    const __nv_bfloat16* Al = g_Ul + ((size_t)b*8192 + m0)*P_;
    const __nv_bfloat16* Bh = g_rh + ((size_t)b*NL   + n0)*P_;
    const __nv_bfloat16* Bl = g_rl + ((size_t)b*NL   + n0)*P_;
    const u32 BUFB = 4*TILE_B;

    int arow  = wm*32 + (lane & 15);
    int acolo = (lane >> 4) * 8;
    int brow  = wn*32 + (lane & 7) + ((lane >> 4) * 8);
    int bcolo = ((lane >> 3) & 1) * 8;

    float acc[2][4][4] = {};

    auto load_chunk = [&](int c, int buf) {
        u32 sbb = uSm + (u32)buf * BUFB;
        int k0 = c * 64;
#pragma unroll
        for (int i = 0; i < 2; i++) {
            int q = t + i*512;
            int row = q >> 3, cc = (q & 7) * 8;
            u32 doff = (u32)(row*SAS + cc) * 2;
            size_t so = (size_t)row * P_ + k0 + cc;
            CPA(sbb + 0*TILE_B + doff, Ah + so);
            CPA(sbb + 1*TILE_B + doff, Al + so);
            CPA(sbb + 2*TILE_B + doff, Bh + so);
            CPA(sbb + 3*TILE_B + doff, Bl + so);
        }
    };

    load_chunk(0, 0); CP_COMMIT();
    for (int c = 0; c < 16; c++) {
        if (c < 15) { load_chunk(c+1, (c+1)&1); CP_COMMIT(); CP_WAIT(1); }
        else        { CP_WAIT(0); }
        __syncthreads();
        u32 u0 = uSm + (u32)(c&1) * BUFB;
        u32 uAh = u0, uAl = u0 + TILE_B, uBh = u0 + 2*TILE_B, uBl = u0 + 3*TILE_B;
#pragma unroll
        for (int ks = 0; ks < 4; ks++) {
            int k = ks * 16;
            u32 aH[2][4], aL[2][4], bH[4][2], bL[4][2];
#pragma unroll
            for (int mt = 0; mt < 2; mt++) {
                u32 off = (u32)(((arow + mt*16)*SAS + k + acolo) * 2);
                ldsm4(aH[mt][0], aH[mt][1], aH[mt][2], aH[mt][3], uAh + off);
                ldsm4(aL[mt][0], aL[mt][1], aL[mt][2], aL[mt][3], uAl + off);
            }
#pragma unroll
            for (int pr = 0; pr < 2; pr++) {
                u32 off = (u32)(((brow + pr*16)*SAS + k + bcolo) * 2);
                ldsm4(bH[2*pr][0], bH[2*pr][1], bH[2*pr+1][0], bH[2*pr+1][1], uBh + off);
                ldsm4(bL[2*pr][0], bL[2*pr][1], bL[2*pr+1][0], bL[2*pr+1][1], uBl + off);
            }
#pragma unroll
            for (int mt = 0; mt < 2; mt++)
#pragma unroll
                for (int nt = 0; nt < 4; nt++) {
                    mma_bf16(acc[mt][nt], aH[mt], bH[nt]);
                    mma_bf16(acc[mt][nt], aH[mt], bL[nt]);
                    mma_bf16(acc[mt][nt], aL[mt], bH[nt]);
                }
        }
        __syncthreads();
    }

    int r = lane >> 2, c2_ = (lane & 3) * 2;
#pragma unroll
    for (int mt = 0; mt < 2; mt++) {
        int gm0 = m0 + wm*32 + mt*16 + r;
        int gm1 = gm0 + 8;
        float pb0 = pb[(size_t)b*8192 + gm0];
        float pb1 = pb[(size_t)b*8192 + gm1];
        const float* ad = g_add + ((size_t)(b*H_) + (gm0 >> 9))*NL;
        float* S0 = S + ((size_t)b*8192 + gm0)*NL;
        float* S1 = S + ((size_t)b*8192 + gm1)*NL;
#pragma unroll
        for (int nt = 0; nt < 4; nt++) {
            int gn = n0 + wn*32 + nt*8 + c2_;
            float2 a2 = *(const float2*)&ad[gn];
            float2 o0, o1;
            o0.x = acc[mt][nt][0] + pb0 + a2.x;
            o0.y = acc[mt][nt][1] + pb0 + a2.y;
            o1.x = acc[mt][nt][2] + pb1 + a2.x;
            o1.y = acc[mt][nt][3] + pb1 + a2.y;
            *(float2*)&S0[gn] = o0;
            *(float2*)&S1[gn] = o1;
        }
    }
}

// ---------------- softmax (512) in place + fp16 copy ----------------
__global__ __launch_bounds__(128) void k_softmax(float* __restrict__ S)
{
    int row = blockIdx.x;
    float* p = S + (size_t)row * NL;
    int t = threadIdx.x;
    float x[4];
    float mx = -INFINITY;
#pragma unroll
    for (int i = 0; i < 4; i++) { x[i] = p[t + i*128]; mx = fmaxf(mx, x[i]); }
    __shared__ float smx[4], ssum[4];
#pragma unroll
    for (int o = 16; o > 0; o >>= 1) mx = fmaxf(mx, __shfl_xor_sync(0xffffffffu, mx, o));
    if ((t & 31) == 0) smx[t >> 5] = mx;
    __syncthreads();
    mx = fmaxf(fmaxf(smx[0], smx[1]), fmaxf(smx[2], smx[3]));
    float s = 0.f;
#pragma unroll
    for (int i = 0; i < 4; i++) { x[i] = expf(x[i] - mx); s += x[i]; }
#pragma unroll
    for (int o = 16; o > 0; o >>= 1) s += __shfl_xor_sync(0xffffffffu, s, o);
    if ((t & 31) == 0) ssum[t >> 5] = s;
    __syncthreads();
    s = ssum[0] + ssum[1] + ssum[2] + ssum[3];
    float inv = 1.0f / s;
    size_t rb = (size_t)row * NL;
#pragma unroll
    for (int i = 0; i < 4; i++) {
        float y = x[i] * inv;
        p[t + i*128] = y;
        g_Sf[rb + t + i*128] = __float2half_rn(y);
    }
}

// ---------------- K2: G = (attn @ c1) * U  (fp16 mma, 512t, dbuf) ---------------
__global__ __launch_bounds__(512, 1) void k_av_mma(const float* __restrict__ U)
{
    extern __shared__ char smraw[];
    u32 uSm = s2u(smraw);
    int t = threadIdx.x, lane = t & 31, wid = t >> 5;
    int wm = wid >> 2, wn = wid & 3;
    int p0 = blockIdx.x * 128, m0 = blockIdx.y * 128, b = blockIdx.z;

    const __half* A  = g_Sf + ((size_t)b*8192 + m0)*NL;
    const __half* Bm = g_tf + ((size_t)b*P_  + p0)*NL;
    const u32 BUFB = 2*TILE_B;

    int arow  = wm*32 + (lane & 15);
    int acolo = (lane >> 4) * 8;
    int brow  = wn*32 + (lane & 7) + ((lane >> 4) * 8);
    int bcolo = ((lane >> 3) & 1) * 8;

    float acc[2][4][4] = {};

    auto load_chunk = [&](int c, int buf) {
        u32 sbb = uSm + (u32)buf * BUFB;
        int k0 = c * 64;
#pragma unroll
        for (int i = 0; i < 2; i++) {
            int q = t + i*512;
            int row = q >> 3, cc = (q & 7) * 8;
            u32 doff = (u32)(row*SAS + cc) * 2;
            size_t so = (size_t)row * NL + k0 + cc;
            CPA(sbb + 0*TILE_B + doff, A  + so);
            CPA(sbb + 1*TILE_B + doff, Bm + so);
        }
    };

    load_chunk(0, 0); CP_COMMIT();
    for (int c = 0; c < 8; c++) {
        if (c < 7) { load_chunk(c+1, (c+1)&1); CP_COMMIT(); CP_WAIT(1); }
        else       { CP_WAIT(0); }
        __syncthreads();
        u32 u0 = uSm + (u32)(c&1) * BUFB;
        u32 uA = u0, uB = u0 + TILE_B;
#pragma unroll
        for (int ks = 0; ks < 4; ks++) {
            int k = ks * 16;
            u32 aF[2][4], bF[4][2];
#pragma unroll
            for (int mt = 0; mt < 2; mt++) {
                u32 off = (u32)(((arow + mt*16)*SAS + k + acolo) * 2);
                ldsm4(aF[mt][0], aF[mt][1], aF[mt][2], aF[mt][3], uA + off);
            }
#pragma unroll
            for (int pr = 0; pr < 2; pr++) {
                u32 off = (u32)(((brow + pr*16)*SAS + k + bcolo) * 2);
                ldsm4(bF[2*pr][0], bF[2*pr][1], bF[2*pr+1][0], bF[2*pr+1][1], uB + off);
            }
#pragma unroll
            for (int mt = 0; mt < 2; mt++)
#pragma unroll
                for (int nt = 0; nt < 4; nt++)
                    mma_f16(acc[mt][nt], aF[mt], bF[nt]);
        }
        __syncthreads();
    }

    int r = lane >> 2, c2_ = (lane & 3) * 2;
#pragma unroll
    for (int mt = 0; mt < 2; mt++) {
        int gm0 = m0 + wm*32 + mt*16 + r;
        size_t ro0 = ((size_t)b*8192 + gm0)*P_;
        size_t ro1 = ro0 + 8*(size_t)P_;
#pragma unroll
        for (int nt = 0; nt < 4; nt++) {
            int gp = p0 + wn*32 + nt*8 + c2_;
            float2 u0 = *(const float2*)&U[ro0 + gp];
            float2 u1 = *(const float2*)&U[ro1 + gp];
            float gx, gy;
            __nv_bfloat16 h0, l0, h1, l1;
            gx = acc[mt][nt][0] * u0.x; gy = acc[mt][nt][1] * u0.y;
            splitbf(gx, h0, l0); splitbf(gy, h1, l1);
            *(__nv_bfloat162*)&g_Gh[ro0 + gp] = __nv_bfloat162(h0, h1);
            *(__nv_bfloat162*)&g_Gl[ro0 + gp] = __nv_bfloat162(l0, l1);
            gx = acc[mt][nt][2] * u1.x; gy = acc[mt][nt][3] * u1.y;
            splitbf(gx, h0, l0); splitbf(gy, h1, l1);
            *(__nv_bfloat162*)&g_Gh[ro1 + gp] = __nv_bfloat162(h0, h1);
            *(__nv_bfloat162*)&g_Gl[ro1 + gp] = __nv_bfloat162(l0, l1);
        }
    }
}

// ---------------- K3: out = G @ w_v^T + attn @ D  (512t, dbuf) ----------
// tile 128(M) x 64(E); 16 warps in 8x2 (M=16, N=32 per warp)
__global__ __launch_bounds__(512, 1) void k_out_mma(float* __restrict__ Out)
{
    extern __shared__ char smraw[];
    u32 uSm = s2u(smraw);
    int t = threadIdx.x, lane = t & 31, wid = t >> 5;
    int wm = wid >> 1, wn = wid & 1;
    int bh = blockIdx.y, h = bh & 15;
    int m0 = blockIdx.x * 128;

    const __nv_bfloat16* GhP = g_Gh + ((size_t)bh*NT + m0)*P_;
    const __nv_bfloat16* GlP = g_Gl + ((size_t)bh*NT + m0)*P_;
    const __nv_bfloat16* WhP = g_Wh + (size_t)h*E_*P_;
    const __nv_bfloat16* WlP = g_Wl + (size_t)h*E_*P_;
    const __half*        Sp  = g_Sf + ((size_t)bh*NT + m0)*NL;
    const __half*        Dp  = g_Df + (size_t)bh*E_*NL;
    const u32 BUFB = 2*TILE_B + 2*HTILE_B;

    int arow  = wm*16 + (lane & 15);
    int acolo = (lane >> 4) * 8;
    int brow  = wn*32 + (lane & 7) + ((lane >> 4) * 8);
    int bcolo = ((lane >> 3) & 1) * 8;

    float acc[4][4] = {};

    // ---- phase 1: G @ W^T, K = 1024, bf16 3-product, dbuf ----
    auto load1 = [&](int c, int buf) {
        u32 sbb = uSm + (u32)buf * BUFB;
        int k0 = c * 64;
#pragma unroll
        for (int i = 0; i < 2; i++) {                 // G tiles: 128 rows
            int q = t + i*512;
            int row = q >> 3, cc = (q & 7) * 8;
            u32 doff = (u32)(row*SAS + cc) * 2;
            size_t so = (size_t)row * P_ + k0 + cc;
            CPA(sbb + 0*TILE_B + doff, GhP + so);
            CPA(sbb + 1*TILE_B + doff, GlP + so);
        }
        {                                             // W tiles: 64 rows
            int row = t >> 3, cc = (t & 7) * 8;
            u32 doff = (u32)(row*SAS + cc) * 2;
            size_t so = (size_t)row * P_ + k0 + cc;
            CPA(sbb + 2*TILE_B + doff, WhP + so);
            CPA(sbb + 2*TILE_B + HTILE_B + doff, WlP + so);
        }
    };

    load1(0, 0); CP_COMMIT();
    for (int c = 0; c < 16; c++) {
        if (c < 15) { load1(c+1, (c+1)&1); CP_COMMIT(); CP_WAIT(1); }
        else        { CP_WAIT(0); }
        __syncthreads();
        u32 u0 = uSm + (u32)(c&1) * BUFB;
        u32 uGh = u0, uGl = u0 + TILE_B, uWh = u0 + 2*TILE_B, uWl = uWh + HTILE_B;
#pragma unroll
        for (int ks = 0; ks < 4; ks++) {
            int k = ks * 16;
            u32 aH[4], aL[4], bH[4][2], bL[4][2];
            {
                u32 off = (u32)((arow*SAS + k + acolo) * 2);
                ldsm4(aH[0], aH[1], aH[2], aH[3], uGh + off);
                ldsm4(aL[0], aL[1], aL[2], aL[3], uGl + off);
            }
#pragma unroll
            for (int pr = 0; pr < 2; pr++) {
                u32 off = (u32)(((brow + pr*16)*SAS + k + bcolo) * 2);
                ldsm4(bH[2*pr][0], bH[2*pr][1], bH[2*pr+1][0], bH[2*pr+1][1], uWh + off);
                ldsm4(bL[2*pr][0], bL[2*pr][1], bL[2*pr+1][0], bL[2*pr+1][1], uWl + off);
            }
#pragma unroll
            for (int nt = 0; nt < 4; nt++) {
                mma_bf16(acc[nt], aH, bH[nt]);
                mma_bf16(acc[nt], aH, bL[nt]);
                mma_bf16(acc[nt], aL, bH[nt]);
            }
        }
        __syncthreads();
    }

    // ---- phase 2: attn @ D^T, K = 512, fp16, dbuf ----
    auto load2 = [&](int c, int buf) {
        u32 sbb = uSm + (u32)buf * BUFB;
        int k0 = c * 64;
#pragma unroll
        for (int i = 0; i < 2; i++) {                 // attn tile: 128 rows
            int q = t + i*512;
            int row = q >> 3, cc = (q & 7) * 8;
            u32 doff = (u32)(row*SAS + cc) * 2;
            CPA(sbb + doff, Sp + (size_t)row * NL + k0 + cc);
        }
        {                                             // D tile: 64 rows
            int row = t >> 3, cc = (t & 7) * 8;
            u32 doff = (u32)(row*SAS + cc) * 2;
            CPA(sbb + TILE_B + doff, Dp + (size_t)row * NL + k0 + cc);
        }
    };

    load2(0, 0); CP_COMMIT();
    for (int c = 0; c < 8; c++) {
        if (c < 7) { load2(c+1, (c+1)&1); CP_COMMIT(); CP_WAIT(1); }
        else       { CP_WAIT(0); }
        __syncthreads();
        u32 u0 = uSm + (u32)(c&1) * BUFB;
        u32 uA = u0, uD = u0 + TILE_B;
#pragma unroll
        for (int ks = 0; ks < 4; ks++) {
            int k = ks * 16;
            u32 aF[4], bF[4][2];
            {
                u32 off = (u32)((arow*SAS + k + acolo) * 2);
                ldsm4(aF[0], aF[1], aF[2], aF[3], uA + off);
            }
#pragma unroll
            for (int pr = 0; pr < 2; pr++) {
                u32 off = (u32)(((brow + pr*16)*SAS + k + bcolo) * 2);
                ldsm4(bF[2*pr][0], bF[2*pr][1], bF[2*pr+1][0], bF[2*pr+1][1], uD + off);
            }
#pragma unroll
            for (int nt = 0; nt < 4; nt++)
                mma_f16(acc[nt], aF, bF[nt]);
        }
        __syncthreads();
    }

    int r = lane >> 2, c2_ = (lane & 3) * 2;
    int gm0 = m0 + wm*16 + r;
    float* O0 = Out + ((size_t)bh*NT + gm0)*E_;
    float* O1 = O0 + 8*(size_t)E_;
#pragma unroll
    for (int nt = 0; nt < 4; nt++) {
        int ge = wn*32 + nt*8 + c2_;
        float2 o0, o1;
        o0.x = acc[nt][0]; o0.y = acc[nt][1];
        o1.x = acc[nt][2]; o1.y = acc[nt][3];
        *(float2*)&O0[ge] = o0;
        *(float2*)&O1[ge] = o1;
    }
}

// ---------------- launch ----------------
extern "C" void kernel_launch(void* const* d_in, const int* in_sizes, int n_in,
                              void* d_out, int out_size)
{
    const float* pu     = (const float*)d_in[0];  // [B,H,Nt,P]
    const float* pb     = (const float*)d_in[1];  // [B,H,Nt,1]
    const float* mu     = (const float*)d_in[2];  // [B,Nl,P]
    const float* logvar = (const float*)d_in[3];  // [B,Nl,P]
    const float* pi     = (const float*)d_in[4];  // [B,Nl,1]
    const float* wv     = (const float*)d_in[5];  // [H,E,P]
    const float* bvv    = (const float*)d_in[6];  // [H,E,Nl]
    const unsigned char* mask = (const unsigned char*)d_in[7]; // [B*H,1,Nl]

    float* out  = (float*)d_out;                  // [BH,Nt,E]
    float* attn = out + (size_t)BH*NT*E_;         // [BH,Nt,Nl]

    __nv_bfloat16 *Uh, *Ul, *Wh, *Wl;
    cudaGetSymbolAddress((void**)&Uh, g_Uh);
    cudaGetSymbolAddress((void**)&Ul, g_Ul);
    cudaGetSymbolAddress((void**)&Wh, g_Wh);
    cudaGetSymbolAddress((void**)&Wl, g_Wl);

    const int SM_SCORES = 2 * 4 * TILE_B;                  // 147456 B
    const int SM_AV     = 2 * 2 * TILE_B;                  // 73728 B
    const int SM_OUT    = 2 * (2 * TILE_B + 2 * HTILE_B);  // 110592 B
    cudaFuncSetAttribute(k_scores_mma, cudaFuncAttributeMaxDynamicSharedMemorySize, SM_SCORES);
    cudaFuncSetAttribute(k_av_mma,     cudaFuncAttributeMaxDynamicSharedMemorySize, SM_AV);
    cudaFuncSetAttribute(k_out_mma,    cudaFuncAttributeMaxDynamicSharedMemorySize, SM_OUT);
    cudaFuncSetAttribute(k_D_mma,      cudaFuncAttributeMaxDynamicSharedMemorySize, SM_OUT);

    k_prep      <<<dim3(NL, B_),     256>>>(mu, logvar, pi, mask);
    k_split     <<<32768,            256>>>(pu, Uh, Ul);
    k_split     <<<1024,             256>>>(wv, Wh, Wl);
    k_D_mma     <<<dim3(NL/128, BH), 512, SM_OUT>>>(bvv);
    k_scores_mma<<<dim3(4, 64, B_),  512, SM_SCORES>>>(pb, attn);
    k_softmax   <<<BH*NT,            128>>>(attn);
    k_av_mma    <<<dim3(8, 64, B_),  512, SM_AV>>>(pu);
    k_out_mma   <<<dim3(NT/128, BH), 512, SM_OUT>>>(out);
}

// round 15
// speedup vs baseline: 1.0354x; 1.0354x over previous
#include <cuda_runtime.h>
#include <cuda_bf16.h>
#include <cuda_fp16.h>
#include <math.h>
#include <stdint.h>

#define B_  4
#define H_  16
#define NT  512
#define NL  512
#define E_  64
#define P_  1024
#define BH  (B_*H_)
#define PRIOR 8.0f

typedef unsigned int u32;

// ---------------- scratch (device globals) ----------------
__device__ __nv_bfloat16 g_Uh[(size_t)B_*8192*P_];  // U split hi  [b*8192+m][p]
__device__ __nv_bfloat16 g_Ul[(size_t)B_*8192*P_];
__device__ __nv_bfloat16 g_rh[B_*NL*P_];            // r = mu/bv hi [b][n][p]
__device__ __nv_bfloat16 g_rl[B_*NL*P_];
__device__ __half        g_tf[B_*P_*NL];            // c1^T fp16 [b][p][n]
__device__ __half        g_Sf[(size_t)BH*NT*NL];    // attn fp16 [bh*Nt+m][n]
__device__ __nv_bfloat16 g_Wh[H_*E_*P_];            // w_v split hi [h*E+e][p]
__device__ __nv_bfloat16 g_Wl[H_*E_*P_];
__device__ __nv_bfloat16 g_Gh[(size_t)BH*NT*P_];    // G split hi [bh*Nt+m][p]
__device__ __nv_bfloat16 g_Gl[(size_t)BH*NT*P_];
__device__ __half        g_Df[(size_t)BH*E_*NL];    // D^T fp16 [bh][e][n]
__device__ float g_add[BH*NL];

// ---------------- helpers ----------------
__device__ __forceinline__ u32 s2u(const void* p) {
    u32 a; asm("{ .reg .u64 t; cvta.to.shared.u64 t, %1; cvt.u32.u64 %0, t; }" : "=r"(a) : "l"(p));
    return a;
}
__device__ __forceinline__ void ldsm4(u32& r0, u32& r1, u32& r2, u32& r3, u32 a) {
    asm volatile("ldmatrix.sync.aligned.m8n8.x4.shared.b16 {%0,%1,%2,%3}, [%4];"
        : "=r"(r0), "=r"(r1), "=r"(r2), "=r"(r3) : "r"(a));
}
__device__ __forceinline__ void mma_bf16(float* c, const u32* a, const u32* b) {
    asm volatile("mma.sync.aligned.m16n8k16.row.col.f32.bf16.bf16.f32 "
        "{%0,%1,%2,%3}, {%4,%5,%6,%7}, {%8,%9}, {%0,%1,%2,%3};"
        : "+f"(c[0]), "+f"(c[1]), "+f"(c[2]), "+f"(c[3])
        : "r"(a[0]), "r"(a[1]), "r"(a[2]), "r"(a[3]), "r"(b[0]), "r"(b[1]));
}
__device__ __forceinline__ void mma_f16(float* c, const u32* a, const u32* b) {
    asm volatile("mma.sync.aligned.m16n8k16.row.col.f32.f16.f16.f32 "
        "{%0,%1,%2,%3}, {%4,%5,%6,%7}, {%8,%9}, {%0,%1,%2,%3};"
        : "+f"(c[0]), "+f"(c[1]), "+f"(c[2]), "+f"(c[3])
        : "r"(a[0]), "r"(a[1]), "r"(a[2]), "r"(a[3]), "r"(b[0]), "r"(b[1]));
}
__device__ __forceinline__ void splitbf(float x, __nv_bfloat16& h, __nv_bfloat16& l) {
    h = __float2bfloat16_rn(x);
    l = __float2bfloat16_rn(x - __bfloat162float(h));
}
#define CPA(s, g)   asm volatile("cp.async.cg.shared.global [%0], [%1], 16;" :: "r"(s), "l"(g) : "memory")
#define CP_COMMIT() asm volatile("cp.async.commit_group;" ::: "memory")
#define CP_WAIT(n)  asm volatile("cp.async.wait_group %0;" :: "n"(n) : "memory")

#define SAS     72                   // padded smem stride (elems)
#define TILE_E  (128*SAS)            // elems per 128-row tile
#define TILE_B  (TILE_E*2)           // bytes
#define HTILE_E (64*SAS)
#define HTILE_B (HTILE_E*2)

// 3-stage pipeline prologue/loop scaffolding:
//   load(0,b0); load(1,b1);
//   iter c: wait(group c done); ONE sync; prefetch c+2 into (c+2)%3; compute c.
// The prefetch target (c+2)%3 == (c-1)%3, whose readers all passed the sync.

// ---------------- K0: per-(b,n) precompute + splits + reductions ----------------
__global__ __launch_bounds__(256) void k_prep(
    const float* __restrict__ mu, const float* __restrict__ logvar,
    const float* __restrict__ pi, const unsigned char* __restrict__ mask)
{
    int n = blockIdx.x, b = blockIdx.y;
    int base = (b*NL + n)*P_;
    int t = threadIdx.x;
    float s2 = 0.f, s3 = 0.f;
#pragma unroll
    for (int i = 0; i < 4; i++) {
        int p = t + i*256;
        float m  = mu[base+p];
        float v  = expf(logvar[base+p]);
        float bv = v + PRIOR;
        float inv = 1.0f / bv;
        float r  = m * inv;
        float c1 = v * inv;
        __nv_bfloat16 h, l;
        splitbf(r, h, l);
        g_rh[base+p] = h; g_rl[base+p] = l;
        g_tf[((size_t)b*P_ + p)*NL + n] = __float2half_rn(c1);
        s2 += m * m * inv;
        s3 += logf(bv);
    }
    __shared__ float red2[8], red3[8];
#pragma unroll
    for (int o = 16; o > 0; o >>= 1) {
        s2 += __shfl_down_sync(0xffffffffu, s2, o);
        s3 += __shfl_down_sync(0xffffffffu, s3, o);
    }
    if ((t & 31) == 0) { red2[t>>5] = s2; red3[t>>5] = s3; }
    __syncthreads();
    __shared__ float sbase;
    if (t == 0) {
        float a2 = 0.f, a3 = 0.f;
        for (int i = 0; i < 8; i++) { a2 += red2[i]; a3 += red3[i]; }
        float piv = pi[b*NL + n];
        float pc  = fmaxf(piv, 1.17549435e-38f);
        sbase = logf(pc) - 0.5f*a2 - 0.5f*a3;
    }
    __syncthreads();
    if (t < H_) {
        float piv = pi[b*NL + n];
        bool msk = (mask[(b*H_ + t)*NL + n] != 0) || (piv <= 0.f);
        g_add[(b*H_ + t)*NL + n] = msk ? -INFINITY : sbase;
    }
}

// ---------------- generic fp32 -> bf16 hi/lo splitter ----------------
__global__ __launch_bounds__(256) void k_split(
    const float* __restrict__ X, __nv_bfloat16* __restrict__ Xh,
    __nv_bfloat16* __restrict__ Xl)
{
    size_t i = ((size_t)blockIdx.x * 256 + threadIdx.x) * 4;
    float4 v = *(const float4*)(X + i);
    __nv_bfloat16 h[4], l[4];
    splitbf(v.x, h[0], l[0]); splitbf(v.y, h[1], l[1]);
    splitbf(v.z, h[2], l[2]); splitbf(v.w, h[3], l[3]);
    uint2 uh, ul;
    uh.x = ((u32)__bfloat16_as_ushort(h[1]) << 16) | __bfloat16_as_ushort(h[0]);
    uh.y = ((u32)__bfloat16_as_ushort(h[3]) << 16) | __bfloat16_as_ushort(h[2]);
    ul.x = ((u32)__bfloat16_as_ushort(l[1]) << 16) | __bfloat16_as_ushort(l[0]);
    ul.y = ((u32)__bfloat16_as_ushort(l[3]) << 16) | __bfloat16_as_ushort(l[2]);
    *(uint2*)&Xh[i] = uh;
    *(uint2*)&Xl[i] = ul;
}

// ---------------- K_D: D^T = 8*(r @ w_v^T) + b_v^T, bf16 mma, 3-stage ----------
// tile 128(n) x 64(e); 8 warps in 4x2 (M=32, N=32 per warp)
__global__ __launch_bounds__(256, 1) void k_D_mma(const float* __restrict__ bvv)
{
    extern __shared__ char smraw[];
    u32 uSm = s2u(smraw);
    int t = threadIdx.x, lane = t & 31, wid = t >> 5;
    int wm = wid >> 1, wn = wid & 1;
    int bh = blockIdx.y, b = bh >> 4, h = bh & 15;
    int m0 = blockIdx.x * 128;                   // n-tile

    const __nv_bfloat16* Ah = g_rh + ((size_t)b*NL + m0)*P_;
    const __nv_bfloat16* Al = g_rl + ((size_t)b*NL + m0)*P_;
    const __nv_bfloat16* WhP = g_Wh + (size_t)h*E_*P_;
    const __nv_bfloat16* WlP = g_Wl + (size_t)h*E_*P_;
    const u32 BUFB = 2*TILE_B + 2*HTILE_B;

    int arow  = wm*32 + (lane & 15);
    int acolo = (lane >> 4) * 8;
    int brow  = wn*32 + (lane & 7) + ((lane >> 4) * 8);
    int bcolo = ((lane >> 3) & 1) * 8;

    float acc[2][4][4] = {};

    auto load_chunk = [&](int c, int buf) {
        u32 sbb = uSm + (u32)buf * BUFB;
        int k0 = c * 64;
#pragma unroll
        for (int i = 0; i < 4; i++) {                 // A tiles: 128 rows
            int q = t + i*256;
            int row = q >> 3, cc = (q & 7) * 8;
            u32 doff = (u32)(row*SAS + cc) * 2;
            size_t so = (size_t)row * P_ + k0 + cc;
            CPA(sbb + 0*TILE_B + doff, Ah + so);
            CPA(sbb + 1*TILE_B + doff, Al + so);
        }
#pragma unroll
        for (int i = 0; i < 2; i++) {                 // W tiles: 64 rows
            int q = t + i*256;
            int row = q >> 3, cc = (q & 7) * 8;
            u32 doff = (u32)(row*SAS + cc) * 2;
            size_t so = (size_t)row * P_ + k0 + cc;
            CPA(sbb + 2*TILE_B + doff, WhP + so);
            CPA(sbb + 2*TILE_B + HTILE_B + doff, WlP + so);
        }
    };

    load_chunk(0, 0); CP_COMMIT();
    load_chunk(1, 1); CP_COMMIT();
    int bufc = 0, bufn = 2;
    for (int c = 0; c < 16; c++) {
        if (c + 1 < 16) { CP_WAIT(1); } else { CP_WAIT(0); }
        __syncthreads();
        if (c + 2 < 16) { load_chunk(c+2, bufn); CP_COMMIT(); }
        u32 u0 = uSm + (u32)bufc * BUFB;
        u32 uAh = u0, uAl = u0 + TILE_B, uWh = u0 + 2*TILE_B, uWl = uWh + HTILE_B;
#pragma unroll
        for (int ks = 0; ks < 4; ks++) {
            int k = ks * 16;
            u32 aH[2][4], aL[2][4], bH[4][2], bL[4][2];
#pragma unroll
            for (int mt = 0; mt < 2; mt++) {
                u32 off = (u32)(((arow + mt*16)*SAS + k + acolo) * 2);
                ldsm4(aH[mt][0], aH[mt][1], aH[mt][2], aH[mt][3], uAh + off);
                ldsm4(aL[mt][0], aL[mt][1], aL[mt][2], aL[mt][3], uAl + off);
            }
#pragma unroll
            for (int pr = 0; pr < 2; pr++) {
                u32 off = (u32)(((brow + pr*16)*SAS + k + bcolo) * 2);
                ldsm4(bH[2*pr][0], bH[2*pr][1], bH[2*pr+1][0], bH[2*pr+1][1], uWh + off);
                ldsm4(bL[2*pr][0], bL[2*pr][1], bL[2*pr+1][0], bL[2*pr+1][1], uWl + off);
            }
#pragma unroll
            for (int mt = 0; mt < 2; mt++)
#pragma unroll
                for (int nt = 0; nt < 4; nt++) {
                    mma_bf16(acc[mt][nt], aH[mt], bH[nt]);
                    mma_bf16(acc[mt][nt], aH[mt], bL[nt]);
                    mma_bf16(acc[mt][nt], aL[mt], bH[nt]);
                }
        }
        bufc = (bufc + 1 == 3) ? 0 : bufc + 1;
        bufn = (bufn + 1 == 3) ? 0 : bufn + 1;
    }

    // epilogue: *8 + b_v^T, transposed fp16 scatter to g_Df[e][n]
    int r = lane >> 2, c2_ = (lane & 3) * 2;
#pragma unroll
    for (int mt = 0; mt < 2; mt++) {
        int gm0 = m0 + wm*32 + mt*16 + r;
        int gm1 = gm0 + 8;
#pragma unroll
        for (int nt = 0; nt < 4; nt++) {
            int ge = wn*32 + nt*8 + c2_;
            size_t be0 = ((size_t)h*E_ + ge)*NL;
            size_t be1 = be0 + NL;
            size_t de0 = ((size_t)bh*E_ + ge)*NL;
            size_t de1 = de0 + NL;
            g_Df[de0 + gm0] = __float2half_rn(PRIOR*acc[mt][nt][0] + bvv[be0 + gm0]);
            g_Df[de1 + gm0] = __float2half_rn(PRIOR*acc[mt][nt][1] + bvv[be1 + gm0]);
            g_Df[de0 + gm1] = __float2half_rn(PRIOR*acc[mt][nt][2] + bvv[be0 + gm1]);
            g_Df[de1 + gm1] = __float2half_rn(PRIOR*acc[mt][nt][3] + bvv[be1 + gm1]);
        }
    }
}

// ---------------- K1: scores, bf16 3-product, 3-stage ----------------
// tile 128(M) x 128(N); 8 warps in 2x4 (M=64, N=32 per warp)
__global__ __launch_bounds__(256, 1) void k_scores_mma(
    const float* __restrict__ pb, float* __restrict__ S)
{
    extern __shared__ char smraw[];
    u32 uSm = s2u(smraw);
    int t = threadIdx.x, lane = t & 31, wid = t >> 5;
    int wm = wid >> 2, wn = wid & 3;
    int n0 = blockIdx.x * 128, m0 = blockIdx.y * 128, b = blockIdx.z;

    const __nv_bfloat16* Ah = g_Uh + ((size_t)b*8192 + m0)*P_;
    const __nv_bfloat16* Al = g_Ul + ((size_t)b*8192 + m0)*P_;
    const __nv_bfloat16* Bh = g_rh + ((size_t)b*NL   + n0)*P_;
    const __nv_bfloat16* Bl = g_rl + ((size_t)b*NL   + n0)*P_;
    const u32 BUFB = 4*TILE_B;

    int arow  = wm*64 + (lane & 15);
    int acolo = (lane >> 4) * 8;
    int brow  = wn*32 + (lane & 7) + ((lane >> 4) * 8);
    int bcolo = ((lane >> 3) & 1) * 8;

    float acc[4][4][4] = {};

    auto load_chunk = [&](int c, int buf) {
        u32 sbb = uSm + (u32)buf * BUFB;
        int k0 = c * 64;
#pragma unroll
        for (int i = 0; i < 4; i++) {
            int q = t + i*256;
            int row = q >> 3, cc = (q & 7) * 8;
            u32 doff = (u32)(row*SAS + cc) * 2;
            size_t so = (size_t)row * P_ + k0 + cc;
            CPA(sbb + 0*TILE_B + doff, Ah + so);
            CPA(sbb + 1*TILE_B + doff, Al + so);
            CPA(sbb + 2*TILE_B + doff, Bh + so);
            CPA(sbb + 3*TILE_B + doff, Bl + so);
        }
    };

    load_chunk(0, 0); CP_COMMIT();
    load_chunk(1, 1); CP_COMMIT();
    int bufc = 0, bufn = 2;
    for (int c = 0; c < 16; c++) {
        if (c + 1 < 16) { CP_WAIT(1); } else { CP_WAIT(0); }
        __syncthreads();
        if (c + 2 < 16) { load_chunk(c+2, bufn); CP_COMMIT(); }
        u32 u0 = uSm + (u32)bufc * BUFB;
        u32 uAh = u0, uAl = u0 + TILE_B, uBh = u0 + 2*TILE_B, uBl = u0 + 3*TILE_B;
#pragma unroll
        for (int ks = 0; ks < 4; ks++) {
            int k = ks * 16;
            u32 aH[4][4], aL[4][4], bH[4][2], bL[4][2];
#pragma unroll
            for (int mt = 0; mt < 4; mt++) {
                u32 off = (u32)(((arow + mt*16)*SAS + k + acolo) * 2);
                ldsm4(aH[mt][0], aH[mt][1], aH[mt][2], aH[mt][3], uAh + off);
                ldsm4(aL[mt][0], aL[mt][1], aL[mt][2], aL[mt][3], uAl + off);
            }
#pragma unroll
            for (int pr = 0; pr < 2; pr++) {
                u32 off = (u32)(((brow + pr*16)*SAS + k + bcolo) * 2);
                ldsm4(bH[2*pr][0], bH[2*pr][1], bH[2*pr+1][0], bH[2*pr+1][1], uBh + off);
                ldsm4(bL[2*pr][0], bL[2*pr][1], bL[2*pr+1][0], bL[2*pr+1][1], uBl + off);
            }
#pragma unroll
            for (int mt = 0; mt < 4; mt++)
#pragma unroll
                for (int nt = 0; nt < 4; nt++) {
                    mma_bf16(acc[mt][nt], aH[mt], bH[nt]);
                    mma_bf16(acc[mt][nt], aH[mt], bL[nt]);
                    mma_bf16(acc[mt][nt], aL[mt], bH[nt]);
                }
        }
        bufc = (bufc + 1 == 3) ? 0 : bufc + 1;
        bufn = (bufn + 1 == 3) ? 0 : bufn + 1;
    }

    int r = lane >> 2, c2_ = (lane & 3) * 2;
#pragma unroll
    for (int mt = 0; mt < 4; mt++) {
        int gm0 = m0 + wm*64 + mt*16 + r;
        int gm1 = gm0 + 8;
        float pb0 = pb[(size_t)b*8192 + gm0];
        float pb1 = pb[(size_t)b*8192 + gm1];
        const float* ad = g_add + ((size_t)(b*H_) + (gm0 >> 9))*NL;
        float* S0 = S + ((size_t)b*8192 + gm0)*NL;
        float* S1 = S + ((size_t)b*8192 + gm1)*NL;
#pragma unroll
        for (int nt = 0; nt < 4; nt++) {
            int gn = n0 + wn*32 + nt*8 + c2_;
            float2 a2 = *(const float2*)&ad[gn];
            float2 o0, o1;
            o0.x = acc[mt][nt][0] + pb0 + a2.x;
            o0.y = acc[mt][nt][1] + pb0 + a2.y;
            o1.x = acc[mt][nt][2] + pb1 + a2.x;
            o1.y = acc[mt][nt][3] + pb1 + a2.y;
            *(float2*)&S0[gn] = o0;
            *(float2*)&S1[gn] = o1;
        }
    }
}

// ---------------- softmax (512) in place + fp16 copy ----------------
__global__ __launch_bounds__(128) void k_softmax(float* __restrict__ S)
{
    int row = blockIdx.x;
    float* p = S + (size_t)row * NL;
    int t = threadIdx.x;
    float x[4];
    float mx = -INFINITY;
#pragma unroll
    for (int i = 0; i < 4; i++) { x[i] = p[t + i*128]; mx = fmaxf(mx, x[i]); }
    __shared__ float smx[4], ssum[4];
#pragma unroll
    for (int o = 16; o > 0; o >>= 1) mx = fmaxf(mx, __shfl_xor_sync(0xffffffffu, mx, o));
    if ((t & 31) == 0) smx[t >> 5] = mx;
    __syncthreads();
    mx = fmaxf(fmaxf(smx[0], smx[1]), fmaxf(smx[2], smx[3]));
    float s = 0.f;
#pragma unroll
    for (int i = 0; i < 4; i++) { x[i] = expf(x[i] - mx); s += x[i]; }
#pragma unroll
    for (int o = 16; o > 0; o >>= 1) s += __shfl_xor_sync(0xffffffffu, s, o);
    if ((t & 31) == 0) ssum[t >> 5] = s;
    __syncthreads();
    s = ssum[0] + ssum[1] + ssum[2] + ssum[3];
    float inv = 1.0f / s;
    size_t rb = (size_t)row * NL;
#pragma unroll
    for (int i = 0; i < 4; i++) {
        float y = x[i] * inv;
        p[t + i*128] = y;
        g_Sf[rb + t + i*128] = __float2half_rn(y);
    }
}

// ---------------- K2: G = (attn @ c1) * U  (fp16 mma, 3-stage) ------------------
// tile 128(M) x 128(P); 8 warps in 2x4 (M=64, N=32 per warp)
__global__ __launch_bounds__(256, 1) void k_av_mma(const float* __restrict__ U)
{
    extern __shared__ char smraw[];
    u32 uSm = s2u(smraw);
    int t = threadIdx.x, lane = t & 31, wid = t >> 5;
    int wm = wid >> 2, wn = wid & 3;
    int p0 = blockIdx.x * 128, m0 = blockIdx.y * 128, b = blockIdx.z;

    const __half* A  = g_Sf + ((size_t)b*8192 + m0)*NL;
    const __half* Bm = g_tf + ((size_t)b*P_  + p0)*NL;
    const u32 BUFB = 2*TILE_B;

    int arow  = wm*64 + (lane & 15);
    int acolo = (lane >> 4) * 8;
    int brow  = wn*32 + (lane & 7) + ((lane >> 4) * 8);
    int bcolo = ((lane >> 3) & 1) * 8;

    float acc[4][4][4] = {};

    auto load_chunk = [&](int c, int buf) {
        u32 sbb = uSm + (u32)buf * BUFB;
        int k0 = c * 64;
#pragma unroll
        for (int i = 0; i < 4; i++) {
            int q = t + i*256;
            int row = q >> 3, cc = (q & 7) * 8;
            u32 doff = (u32)(row*SAS + cc) * 2;
            size_t so = (size_t)row * NL + k0 + cc;
            CPA(sbb + 0*TILE_B + doff, A  + so);
            CPA(sbb + 1*TILE_B + doff, Bm + so);
        }
    };

    load_chunk(0, 0); CP_COMMIT();
    load_chunk(1, 1); CP_COMMIT();
    int bufc = 0, bufn = 2;
    for (int c = 0; c < 8; c++) {
        if (c + 1 < 8) { CP_WAIT(1); } else { CP_WAIT(0); }
        __syncthreads();
        if (c + 2 < 8) { load_chunk(c+2, bufn); CP_COMMIT(); }
        u32 u0 = uSm + (u32)bufc * BUFB;
        u32 uA = u0, uB = u0 + TILE_B;
#pragma unroll
        for (int ks = 0; ks < 4; ks++) {
            int k = ks * 16;
            u32 aF[4][4], bF[4][2];
#pragma unroll
            for (int mt = 0; mt < 4; mt++) {
                u32 off = (u32)(((arow + mt*16)*SAS + k + acolo) * 2);
                ldsm4(aF[mt][0], aF[mt][1], aF[mt][2], aF[mt][3], uA + off);
            }
#pragma unroll
            for (int pr = 0; pr < 2; pr++) {
                u32 off = (u32)(((brow + pr*16)*SAS + k + bcolo) * 2);
                ldsm4(bF[2*pr][0], bF[2*pr][1], bF[2*pr+1][0], bF[2*pr+1][1], uB + off);
            }
#pragma unroll
            for (int mt = 0; mt < 4; mt++)
#pragma unroll
                for (int nt = 0; nt < 4; nt++)
                    mma_f16(acc[mt][nt], aF[mt], bF[nt]);
        }
        bufc = (bufc + 1 == 3) ? 0 : bufc + 1;
        bufn = (bufn + 1 == 3) ? 0 : bufn + 1;
    }

    int r = lane >> 2, c2_ = (lane & 3) * 2;
#pragma unroll
    for (int mt = 0; mt < 4; mt++) {
        int gm0 = m0 + wm*64 + mt*16 + r;
        size_t ro0 = ((size_t)b*8192 + gm0)*P_;
        size_t ro1 = ro0 + 8*(size_t)P_;
#pragma unroll
        for (int nt = 0; nt < 4; nt++) {
            int gp = p0 + wn*32 + nt*8 + c2_;
            float2 u0 = *(const float2*)&U[ro0 + gp];
            float2 u1 = *(const float2*)&U[ro1 + gp];
            float gx, gy;
            __nv_bfloat16 h0, l0, h1, l1;
            gx = acc[mt][nt][0] * u0.x; gy = acc[mt][nt][1] * u0.y;
            splitbf(gx, h0, l0); splitbf(gy, h1, l1);
            *(__nv_bfloat162*)&g_Gh[ro0 + gp] = __nv_bfloat162(h0, h1);
            *(__nv_bfloat162*)&g_Gl[ro0 + gp] = __nv_bfloat162(l0, l1);
            gx = acc[mt][nt][2] * u1.x; gy = acc[mt][nt][3] * u1.y;
            splitbf(gx, h0, l0); splitbf(gy, h1, l1);
            *(__nv_bfloat162*)&g_Gh[ro1 + gp] = __nv_bfloat162(h0, h1);
            *(__nv_bfloat162*)&g_Gl[ro1 + gp] = __nv_bfloat162(l0, l1);
        }
    }
}

// ---------------- K3: out = G @ w_v^T + attn @ D  (3-stage, two phases) ---------
// tile 128(M) x 64(E); 8 warps in 4x2 (M=32, N=32 per warp)
__global__ __launch_bounds__(256, 1) void k_out_mma(float* __restrict__ Out)
{
    extern __shared__ char smraw[];
    u32 uSm = s2u(smraw);
    int t = threadIdx.x, lane = t & 31, wid = t >> 5;
    int wm = wid >> 1, wn = wid & 1;
    int bh = blockIdx.y, h = bh & 15;
    int m0 = blockIdx.x * 128;

    const __nv_bfloat16* GhP = g_Gh + ((size_t)bh*NT + m0)*P_;
    const __nv_bfloat16* GlP = g_Gl + ((size_t)bh*NT + m0)*P_;
    const __nv_bfloat16* WhP = g_Wh + (size_t)h*E_*P_;
    const __nv_bfloat16* WlP = g_Wl + (size_t)h*E_*P_;
    const __half*        Sp  = g_Sf + ((size_t)bh*NT + m0)*NL;
    const __half*        Dp  = g_Df + (size_t)bh*E_*NL;
    const u32 BUFB = 2*TILE_B + 2*HTILE_B;

    int arow  = wm*32 + (lane & 15);
    int acolo = (lane >> 4) * 8;
    int brow  = wn*32 + (lane & 7) + ((lane >> 4) * 8);
    int bcolo = ((lane >> 3) & 1) * 8;

    float acc[2][4][4] = {};

    // ---- phase 1: G @ W^T, K = 1024, bf16 3-product, 3-stage ----
    auto load1 = [&](int c, int buf) {
        u32 sbb = uSm + (u32)buf * BUFB;
        int k0 = c * 64;
#pragma unroll
        for (int i = 0; i < 4; i++) {                 // G tiles: 128 rows
            int q = t + i*256;
            int row = q >> 3, cc = (q & 7) * 8;
            u32 doff = (u32)(row*SAS + cc) * 2;
            size_t so = (size_t)row * P_ + k0 + cc;
            CPA(sbb + 0*TILE_B + doff, GhP + so);
            CPA(sbb + 1*TILE_B + doff, GlP + so);
        }
#pragma unroll
        for (int i = 0; i < 2; i++) {                 // W tiles: 64 rows
            int q = t + i*256;
            int row = q >> 3, cc = (q & 7) * 8;
            u32 doff = (u32)(row*SAS + cc) * 2;
            size_t so = (size_t)row * P_ + k0 + cc;
            CPA(sbb + 2*TILE_B + doff, WhP + so);
            CPA(sbb + 2*TILE_B + HTILE_B + doff, WlP + so);
        }
    };

    load1(0, 0); CP_COMMIT();
    load1(1, 1); CP_COMMIT();
    int bufc = 0, bufn = 2;
    for (int c = 0; c < 16; c++) {
        if (c + 1 < 16) { CP_WAIT(1); } else { CP_WAIT(0); }
        __syncthreads();
        if (c + 2 < 16) { load1(c+2, bufn); CP_COMMIT(); }
        u32 u0 = uSm + (u32)bufc * BUFB;
        u32 uGh = u0, uGl = u0 + TILE_B, uWh = u0 + 2*TILE_B, uWl = uWh + HTILE_B;
#pragma unroll
        for (int ks = 0; ks < 4; ks++) {
            int k = ks * 16;
            u32 aH[2][4], aL[2][4], bH[4][2], bL[4][2];
#pragma unroll
            for (int mt = 0; mt < 2; mt++) {
                u32 off = (u32)(((arow + mt*16)*SAS + k + acolo) * 2);
                ldsm4(aH[mt][0], aH[mt][1], aH[mt][2], aH[mt][3], uGh + off);
                ldsm4(aL[mt][0], aL[mt][1], aL[mt][2], aL[mt][3], uGl + off);
            }
#pragma unroll
            for (int pr = 0; pr < 2; pr++) {
                u32 off = (u32)(((brow + pr*16)*SAS + k + bcolo) * 2);
                ldsm4(bH[2*pr][0], bH[2*pr][1], bH[2*pr+1][0], bH[2*pr+1][1], uWh + off);
                ldsm4(bL[2*pr][0], bL[2*pr][1], bL[2*pr+1][0], bL[2*pr+1][1], uWl + off);
            }
#pragma unroll
            for (int mt = 0; mt < 2; mt++)
#pragma unroll
                for (int nt = 0; nt < 4; nt++) {
                    mma_bf16(acc[mt][nt], aH[mt], bH[nt]);
                    mma_bf16(acc[mt][nt], aH[mt], bL[nt]);
                    mma_bf16(acc[mt][nt], aL[mt], bH[nt]);
                }
        }
        bufc = (bufc + 1 == 3) ? 0 : bufc + 1;
        bufn = (bufn + 1 == 3) ? 0 : bufn + 1;
    }

    // barrier: phase-2 prologue writes buffers phase-1 tail may still read
    __syncthreads();

    // ---- phase 2: attn @ D^T, K = 512, fp16, 3-stage ----
    auto load2 = [&](int c, int buf) {
        u32 sbb = uSm + (u32)buf * BUFB;
        int k0 = c * 64;
#pragma unroll
        for (int i = 0; i < 4; i++) {                 // attn tile: 128 rows
            int q = t + i*256;
            int row = q >> 3, cc = (q & 7) * 8;
            u32 doff = (u32)(row*SAS + cc) * 2;
            CPA(sbb + doff, Sp + (size_t)row * NL + k0 + cc);
        }
#pragma unroll
        for (int i = 0; i < 2; i++) {                 // D tile: 64 rows
            int q = t + i*256;
            int row = q >> 3, cc = (q & 7) * 8;
            u32 doff = (u32)(row*SAS + cc) * 2;
            CPA(sbb + TILE_B + doff, Dp + (size_t)row * NL + k0 + cc);
        }
    };

    load2(0, 0); CP_COMMIT();
    load2(1, 1); CP_COMMIT();
    bufc = 0; bufn = 2;
    for (int c = 0; c < 8; c++) {
        if (c + 1 < 8) { CP_WAIT(1); } else { CP_WAIT(0); }
        __syncthreads();
        if (c + 2 < 8) { load2(c+2, bufn); CP_COMMIT(); }
        u32 u0 = uSm + (u32)bufc * BUFB;
        u32 uA = u0, uD = u0 + TILE_B;
#pragma unroll
        for (int ks = 0; ks < 4; ks++) {
            int k = ks * 16;
            u32 aF[2][4], bF[4][2];
#pragma unroll
            for (int mt = 0; mt < 2; mt++) {
                u32 off = (u32)(((arow + mt*16)*SAS + k + acolo) * 2);
                ldsm4(aF[mt][0], aF[mt][1], aF[mt][2], aF[mt][3], uA + off);
            }
#pragma unroll
            for (int pr = 0; pr < 2; pr++) {
                u32 off = (u32)(((brow + pr*16)*SAS + k + bcolo) * 2);
                ldsm4(bF[2*pr][0], bF[2*pr][1], bF[2*pr+1][0], bF[2*pr+1][1], uD + off);
            }
#pragma unroll
            for (int mt = 0; mt < 2; mt++)
#pragma unroll
                for (int nt = 0; nt < 4; nt++)
                    mma_f16(acc[mt][nt], aF[mt], bF[nt]);
        }
        bufc = (bufc + 1 == 3) ? 0 : bufc + 1;
        bufn = (bufn + 1 == 3) ? 0 : bufn + 1;
    }

    int r = lane >> 2, c2_ = (lane & 3) * 2;
#pragma unroll
    for (int mt = 0; mt < 2; mt++) {
        int gm0 = m0 + wm*32 + mt*16 + r;
        float* O0 = Out + ((size_t)bh*NT + gm0)*E_;
        float* O1 = O0 + 8*(size_t)E_;
#pragma unroll
        for (int nt = 0; nt < 4; nt++) {
            int ge = wn*32 + nt*8 + c2_;
            float2 o0, o1;
            o0.x = acc[mt][nt][0]; o0.y = acc[mt][nt][1];
            o1.x = acc[mt][nt][2]; o1.y = acc[mt][nt][3];
            *(float2*)&O0[ge] = o0;
            *(float2*)&O1[ge] = o1;
        }
    }
}

// ---------------- launch ----------------
extern "C" void kernel_launch(void* const* d_in, const int* in_sizes, int n_in,
                              void* d_out, int out_size)
{
    const float* pu     = (const float*)d_in[0];  // [B,H,Nt,P]
    const float* pb     = (const float*)d_in[1];  // [B,H,Nt,1]
    const float* mu     = (const float*)d_in[2];  // [B,Nl,P]
    const float* logvar = (const float*)d_in[3];  // [B,Nl,P]
    const float* pi     = (const float*)d_in[4];  // [B,Nl,1]
    const float* wv     = (const float*)d_in[5];  // [H,E,P]
    const float* bvv    = (const float*)d_in[6];  // [H,E,Nl]
    const unsigned char* mask = (const unsigned char*)d_in[7]; // [B*H,1,Nl]

    float* out  = (float*)d_out;                  // [BH,Nt,E]
    float* attn = out + (size_t)BH*NT*E_;         // [BH,Nt,Nl]

    __nv_bfloat16 *Uh, *Ul, *Wh, *Wl;
    cudaGetSymbolAddress((void**)&Uh, g_Uh);
    cudaGetSymbolAddress((void**)&Ul, g_Ul);
    cudaGetSymbolAddress((void**)&Wh, g_Wh);
    cudaGetSymbolAddress((void**)&Wl, g_Wl);

    const int SM_SCORES = 3 * 4 * TILE_B;                  // 221184 B (3-stage)
    const int SM_AV     = 3 * 2 * TILE_B;                  // 110592 B
    const int SM_OUT    = 3 * (2 * TILE_B + 2 * HTILE_B);  // 165888 B
    cudaFuncSetAttribute(k_scores_mma, cudaFuncAttributeMaxDynamicSharedMemorySize, SM_SCORES);
    cudaFuncSetAttribute(k_av_mma,     cudaFuncAttributeMaxDynamicSharedMemorySize, SM_AV);
    cudaFuncSetAttribute(k_out_mma,    cudaFuncAttributeMaxDynamicSharedMemorySize, SM_OUT);
    cudaFuncSetAttribute(k_D_mma,      cudaFuncAttributeMaxDynamicSharedMemorySize, SM_OUT);

    k_prep      <<<dim3(NL, B_),     256>>>(mu, logvar, pi, mask);
    k_split     <<<32768,            256>>>(pu, Uh, Ul);
    k_split     <<<1024,             256>>>(wv, Wh, Wl);
    k_D_mma     <<<dim3(NL/128, BH), 256, SM_OUT>>>(bvv);
    k_scores_mma<<<dim3(4, 64, B_),  256, SM_SCORES>>>(pb, attn);
    k_softmax   <<<BH*NT,            128>>>(attn);
    k_av_mma    <<<dim3(8, 64, B_),  256, SM_AV>>>(pu);
    k_out_mma   <<<dim3(NT/128, BH), 256, SM_OUT>>>(out);
}

// round 16
// speedup vs baseline: 1.0782x; 1.0413x over previous
#include <cuda_runtime.h>
#include <cuda_bf16.h>
#include <cuda_fp16.h>
#include <math.h>
#include <stdint.h>

#define B_  4
#define H_  16
#define NT  512
#define NL  512
#define E_  64
#define P_  1024
#define BH  (B_*H_)
#define PRIOR 8.0f

typedef unsigned int u32;

// ---------------- scratch (device globals) ----------------
__device__ __nv_bfloat16 g_Uh[(size_t)B_*8192*P_];  // U split hi  [b*8192+m][p]
__device__ __nv_bfloat16 g_Ul[(size_t)B_*8192*P_];
__device__ __nv_bfloat16 g_rh[B_*NL*P_];            // r = mu/bv hi [b][n][p]
__device__ __nv_bfloat16 g_rl[B_*NL*P_];
__device__ __half        g_tf[B_*P_*NL];            // c1^T fp16 [b][p][n]
__device__ __half        g_Sf[(size_t)BH*NT*NL];    // attn fp16 [bh*Nt+m][n]
__device__ __nv_bfloat16 g_Wh[H_*E_*P_];            // w_v split hi [h*E+e][p]
__device__ __nv_bfloat16 g_Wl[H_*E_*P_];
__device__ __half        g_Df[(size_t)BH*E_*NL];    // D^T fp16 [bh][e][n]
__device__ float g_add[BH*NL];

// ---------------- helpers ----------------
__device__ __forceinline__ u32 s2u(const void* p) {
    u32 a; asm("{ .reg .u64 t; cvta.to.shared.u64 t, %1; cvt.u32.u64 %0, t; }" : "=r"(a) : "l"(p));
    return a;
}
__device__ __forceinline__ void ldsm4(u32& r0, u32& r1, u32& r2, u32& r3, u32 a) {
    asm volatile("ldmatrix.sync.aligned.m8n8.x4.shared.b16 {%0,%1,%2,%3}, [%4];"
        : "=r"(r0), "=r"(r1), "=r"(r2), "=r"(r3) : "r"(a));
}
__device__ __forceinline__ void mma_bf16(float* c, const u32* a, const u32* b) {
    asm volatile("mma.sync.aligned.m16n8k16.row.col.f32.bf16.bf16.f32 "
        "{%0,%1,%2,%3}, {%4,%5,%6,%7}, {%8,%9}, {%0,%1,%2,%3};"
        : "+f"(c[0]), "+f"(c[1]), "+f"(c[2]), "+f"(c[3])
        : "r"(a[0]), "r"(a[1]), "r"(a[2]), "r"(a[3]), "r"(b[0]), "r"(b[1]));
}
__device__ __forceinline__ void mma_f16(float* c, const u32* a, const u32* b) {
    asm volatile("mma.sync.aligned.m16n8k16.row.col.f32.f16.f16.f32 "
        "{%0,%1,%2,%3}, {%4,%5,%6,%7}, {%8,%9}, {%0,%1,%2,%3};"
        : "+f"(c[0]), "+f"(c[1]), "+f"(c[2]), "+f"(c[3])
        : "r"(a[0]), "r"(a[1]), "r"(a[2]), "r"(a[3]), "r"(b[0]), "r"(b[1]));
}
__device__ __forceinline__ void splitbf(float x, __nv_bfloat16& h, __nv_bfloat16& l) {
    h = __float2bfloat16_rn(x);
    l = __float2bfloat16_rn(x - __bfloat162float(h));
}
#define CPA(s, g)   asm volatile("cp.async.cg.shared.global [%0], [%1], 16;" :: "r"(s), "l"(g) : "memory")
#define CP_COMMIT() asm volatile("cp.async.commit_group;" ::: "memory")
#define CP_WAIT(n)  asm volatile("cp.async.wait_group %0;" :: "n"(n) : "memory")

#define SAS     72                   // padded smem stride (elems)
#define TILE_E  (128*SAS)            // elems per 128-row tile
#define TILE_B  (TILE_E*2)           // bytes

// fused kernel smem layout (all 64-col chunks, stride SAS)
#define CH      (64*SAS*2)           // 9216 B : [64 rows x 64 cols] fp16/bf16
#define C1CH    (128*SAS*2)          // 18432 B: [128 rows x 64 cols]
#define ATT_OFF 0                    // 8 x CH  = 73728 (attn resident)
#define C1_OFF  (8*CH)               // 3 x C1CH = 55296 (c1 ring; D ring reuses)
#define WS_OFF  (C1_OFF + 3*C1CH)    // 4 x CH = 36864 (Wh c0,c1, Wl c0,c1)
#define GT_OFF  (WS_OFF + 4*CH)      // 4 x CH = 36864 (Gh c0,c1, Gl c0,c1)
#define SM_FUSED (GT_OFF + 4*CH)     // 202752 B

// ---------------- K0: per-(b,n) precompute + splits + reductions ----------------
__global__ __launch_bounds__(256) void k_prep(
    const float* __restrict__ mu, const float* __restrict__ logvar,
    const float* __restrict__ pi, const unsigned char* __restrict__ mask)
{
    int n = blockIdx.x, b = blockIdx.y;
    int base = (b*NL + n)*P_;
    int t = threadIdx.x;
    float s2 = 0.f, s3 = 0.f;
#pragma unroll
    for (int i = 0; i < 4; i++) {
        int p = t + i*256;
        float m  = mu[base+p];
        float v  = expf(logvar[base+p]);
        float bv = v + PRIOR;
        float inv = 1.0f / bv;
        float r  = m * inv;
        float c1 = v * inv;
        __nv_bfloat16 h, l;
        splitbf(r, h, l);
        g_rh[base+p] = h; g_rl[base+p] = l;
        g_tf[((size_t)b*P_ + p)*NL + n] = __float2half_rn(c1);
        s2 += m * m * inv;
        s3 += logf(bv);
    }
    __shared__ float red2[8], red3[8];
#pragma unroll
    for (int o = 16; o > 0; o >>= 1) {
        s2 += __shfl_down_sync(0xffffffffu, s2, o);
        s3 += __shfl_down_sync(0xffffffffu, s3, o);
    }
    if ((t & 31) == 0) { red2[t>>5] = s2; red3[t>>5] = s3; }
    __syncthreads();
    __shared__ float sbase;
    if (t == 0) {
        float a2 = 0.f, a3 = 0.f;
        for (int i = 0; i < 8; i++) { a2 += red2[i]; a3 += red3[i]; }
        float piv = pi[b*NL + n];
        float pc  = fmaxf(piv, 1.17549435e-38f);
        sbase = logf(pc) - 0.5f*a2 - 0.5f*a3;
    }
    __syncthreads();
    if (t < H_) {
        float piv = pi[b*NL + n];
        bool msk = (mask[(b*H_ + t)*NL + n] != 0) || (piv <= 0.f);
        g_add[(b*H_ + t)*NL + n] = msk ? -INFINITY : sbase;
    }
}

// ---------------- generic fp32 -> bf16 hi/lo splitter ----------------
__global__ __launch_bounds__(256) void k_split(
    const float* __restrict__ X, __nv_bfloat16* __restrict__ Xh,
    __nv_bfloat16* __restrict__ Xl)
{
    size_t i = ((size_t)blockIdx.x * 256 + threadIdx.x) * 4;
    float4 v = *(const float4*)(X + i);
    __nv_bfloat16 h[4], l[4];
    splitbf(v.x, h[0], l[0]); splitbf(v.y, h[1], l[1]);
    splitbf(v.z, h[2], l[2]); splitbf(v.w, h[3], l[3]);
    uint2 uh, ul;
    uh.x = ((u32)__bfloat16_as_ushort(h[1]) << 16) | __bfloat16_as_ushort(h[0]);
    uh.y = ((u32)__bfloat16_as_ushort(h[3]) << 16) | __bfloat16_as_ushort(h[2]);
    ul.x = ((u32)__bfloat16_as_ushort(l[1]) << 16) | __bfloat16_as_ushort(l[0]);
    ul.y = ((u32)__bfloat16_as_ushort(l[3]) << 16) | __bfloat16_as_ushort(l[2]);
    *(uint2*)&Xh[i] = uh;
    *(uint2*)&Xl[i] = ul;
}

// ---------------- K_D: D^T = 8*(r @ w_v^T) + b_v^T, bf16 mma, 3-stage ----------
#define HTILE_B (64*SAS*2)
__global__ __launch_bounds__(256, 1) void k_D_mma(const float* __restrict__ bvv)
{
    extern __shared__ char smraw[];
    u32 uSm = s2u(smraw);
    int t = threadIdx.x, lane = t & 31, wid = t >> 5;
    int wm = wid >> 1, wn = wid & 1;
    int bh = blockIdx.y, b = bh >> 4, h = bh & 15;
    int m0 = blockIdx.x * 128;                   // n-tile

    const __nv_bfloat16* Ah = g_rh + ((size_t)b*NL + m0)*P_;
    const __nv_bfloat16* Al = g_rl + ((size_t)b*NL + m0)*P_;
    const __nv_bfloat16* WhP = g_Wh + (size_t)h*E_*P_;
    const __nv_bfloat16* WlP = g_Wl + (size_t)h*E_*P_;
    const u32 BUFB = 2*TILE_B + 2*HTILE_B;

    int arow  = wm*32 + (lane & 15);
    int acolo = (lane >> 4) * 8;
    int brow  = wn*32 + (lane & 7) + ((lane >> 4) * 8);
    int bcolo = ((lane >> 3) & 1) * 8;

    float acc[2][4][4] = {};

    auto load_chunk = [&](int c, int buf) {
        u32 sbb = uSm + (u32)buf * BUFB;
        int k0 = c * 64;
#pragma unroll
        for (int i = 0; i < 4; i++) {
            int q = t + i*256;
            int row = q >> 3, cc = (q & 7) * 8;
            u32 doff = (u32)(row*SAS + cc) * 2;
            size_t so = (size_t)row * P_ + k0 + cc;
            CPA(sbb + 0*TILE_B + doff, Ah + so);
            CPA(sbb + 1*TILE_B + doff, Al + so);
        }
#pragma unroll
        for (int i = 0; i < 2; i++) {
            int q = t + i*256;
            int row = q >> 3, cc = (q & 7) * 8;
            u32 doff = (u32)(row*SAS + cc) * 2;
            size_t so = (size_t)row * P_ + k0 + cc;
            CPA(sbb + 2*TILE_B + doff, WhP + so);
            CPA(sbb + 2*TILE_B + HTILE_B + doff, WlP + so);
        }
    };

    load_chunk(0, 0); CP_COMMIT();
    load_chunk(1, 1); CP_COMMIT();
    int bufc = 0, bufn = 2;
    for (int c = 0; c < 16; c++) {
        if (c + 1 < 16) { CP_WAIT(1); } else { CP_WAIT(0); }
        __syncthreads();
        if (c + 2 < 16) { load_chunk(c+2, bufn); CP_COMMIT(); }
        u32 u0 = uSm + (u32)bufc * BUFB;
        u32 uAh = u0, uAl = u0 + TILE_B, uWh = u0 + 2*TILE_B, uWl = uWh + HTILE_B;
#pragma unroll
        for (int ks = 0; ks < 4; ks++) {
            int k = ks * 16;
            u32 aH[2][4], aL[2][4], bH[4][2], bL[4][2];
#pragma unroll
            for (int mt = 0; mt < 2; mt++) {
                u32 off = (u32)(((arow + mt*16)*SAS + k + acolo) * 2);
                ldsm4(aH[mt][0], aH[mt][1], aH[mt][2], aH[mt][3], uAh + off);
                ldsm4(aL[mt][0], aL[mt][1], aL[mt][2], aL[mt][3], uAl + off);
            }
#pragma unroll
            for (int pr = 0; pr < 2; pr++) {
                u32 off = (u32)(((brow + pr*16)*SAS + k + bcolo) * 2);
                ldsm4(bH[2*pr][0], bH[2*pr][1], bH[2*pr+1][0], bH[2*pr+1][1], uWh + off);
                ldsm4(bL[2*pr][0], bL[2*pr][1], bL[2*pr+1][0], bL[2*pr+1][1], uWl + off);
            }
#pragma unroll
            for (int mt = 0; mt < 2; mt++)
#pragma unroll
                for (int nt = 0; nt < 4; nt++) {
                    mma_bf16(acc[mt][nt], aH[mt], bH[nt]);
                    mma_bf16(acc[mt][nt], aH[mt], bL[nt]);
                    mma_bf16(acc[mt][nt], aL[mt], bH[nt]);
                }
        }
        bufc = (bufc + 1 == 3) ? 0 : bufc + 1;
        bufn = (bufn + 1 == 3) ? 0 : bufn + 1;
    }

    int r = lane >> 2, c2_ = (lane & 3) * 2;
#pragma unroll
    for (int mt = 0; mt < 2; mt++) {
        int gm0 = m0 + wm*32 + mt*16 + r;
        int gm1 = gm0 + 8;
#pragma unroll
        for (int nt = 0; nt < 4; nt++) {
            int ge = wn*32 + nt*8 + c2_;
            size_t be0 = ((size_t)h*E_ + ge)*NL;
            size_t be1 = be0 + NL;
            size_t de0 = ((size_t)bh*E_ + ge)*NL;
            size_t de1 = de0 + NL;
            g_Df[de0 + gm0] = __float2half_rn(PRIOR*acc[mt][nt][0] + bvv[be0 + gm0]);
            g_Df[de1 + gm0] = __float2half_rn(PRIOR*acc[mt][nt][1] + bvv[be1 + gm0]);
            g_Df[de0 + gm1] = __float2half_rn(PRIOR*acc[mt][nt][2] + bvv[be0 + gm1]);
            g_Df[de1 + gm1] = __float2half_rn(PRIOR*acc[mt][nt][3] + bvv[be1 + gm1]);
        }
    }
}

// ---------------- K1: scores, bf16 3-product, 3-stage (unchanged R15) ----------
__global__ __launch_bounds__(256, 1) void k_scores_mma(
    const float* __restrict__ pb, float* __restrict__ S)
{
    extern __shared__ char smraw[];
    u32 uSm = s2u(smraw);
    int t = threadIdx.x, lane = t & 31, wid = t >> 5;
    int wm = wid >> 2, wn = wid & 3;
    int n0 = blockIdx.x * 128, m0 = blockIdx.y * 128, b = blockIdx.z;

    const __nv_bfloat16* Ah = g_Uh + ((size_t)b*8192 + m0)*P_;
    const __nv_bfloat16* Al = g_Ul + ((size_t)b*8192 + m0)*P_;
    const __nv_bfloat16* Bh = g_rh + ((size_t)b*NL   + n0)*P_;
    const __nv_bfloat16* Bl = g_rl + ((size_t)b*NL   + n0)*P_;
    const u32 BUFB = 4*TILE_B;

    int arow  = wm*64 + (lane & 15);
    int acolo = (lane >> 4) * 8;
    int brow  = wn*32 + (lane & 7) + ((lane >> 4) * 8);
    int bcolo = ((lane >> 3) & 1) * 8;

    float acc[4][4][4] = {};

    auto load_chunk = [&](int c, int buf) {
        u32 sbb = uSm + (u32)buf * BUFB;
        int k0 = c * 64;
#pragma unroll
        for (int i = 0; i < 4; i++) {
            int q = t + i*256;
            int row = q >> 3, cc = (q & 7) * 8;
            u32 doff = (u32)(row*SAS + cc) * 2;
            size_t so = (size_t)row * P_ + k0 + cc;
            CPA(sbb + 0*TILE_B + doff, Ah + so);
            CPA(sbb + 1*TILE_B + doff, Al + so);
            CPA(sbb + 2*TILE_B + doff, Bh + so);
            CPA(sbb + 3*TILE_B + doff, Bl + so);
        }
    };

    load_chunk(0, 0); CP_COMMIT();
    load_chunk(1, 1); CP_COMMIT();
    int bufc = 0, bufn = 2;
    for (int c = 0; c < 16; c++) {
        if (c + 1 < 16) { CP_WAIT(1); } else { CP_WAIT(0); }
        __syncthreads();
        if (c + 2 < 16) { load_chunk(c+2, bufn); CP_COMMIT(); }
        u32 u0 = uSm + (u32)bufc * BUFB;
        u32 uAh = u0, uAl = u0 + TILE_B, uBh = u0 + 2*TILE_B, uBl = u0 + 3*TILE_B;
#pragma unroll
        for (int ks = 0; ks < 4; ks++) {
            int k = ks * 16;
            u32 aH[4][4], aL[4][4], bH[4][2], bL[4][2];
#pragma unroll
            for (int mt = 0; mt < 4; mt++) {
                u32 off = (u32)(((arow + mt*16)*SAS + k + acolo) * 2);
                ldsm4(aH[mt][0], aH[mt][1], aH[mt][2], aH[mt][3], uAh + off);
                ldsm4(aL[mt][0], aL[mt][1], aL[mt][2], aL[mt][3], uAl + off);
            }
#pragma unroll
            for (int pr = 0; pr < 2; pr++) {
                u32 off = (u32)(((brow + pr*16)*SAS + k + bcolo) * 2);
                ldsm4(bH[2*pr][0], bH[2*pr][1], bH[2*pr+1][0], bH[2*pr+1][1], uBh + off);
                ldsm4(bL[2*pr][0], bL[2*pr][1], bL[2*pr+1][0], bL[2*pr+1][1], uBl + off);
            }
#pragma unroll
            for (int mt = 0; mt < 4; mt++)
#pragma unroll
                for (int nt = 0; nt < 4; nt++) {
                    mma_bf16(acc[mt][nt], aH[mt], bH[nt]);
                    mma_bf16(acc[mt][nt], aH[mt], bL[nt]);
                    mma_bf16(acc[mt][nt], aL[mt], bH[nt]);
                }
        }
        bufc = (bufc + 1 == 3) ? 0 : bufc + 1;
        bufn = (bufn + 1 == 3) ? 0 : bufn + 1;
    }

    int r = lane >> 2, c2_ = (lane & 3) * 2;
#pragma unroll
    for (int mt = 0; mt < 4; mt++) {
        int gm0 = m0 + wm*64 + mt*16 + r;
        int gm1 = gm0 + 8;
        float pb0 = pb[(size_t)b*8192 + gm0];
        float pb1 = pb[(size_t)b*8192 + gm1];
        const float* ad = g_add + ((size_t)(b*H_) + (gm0 >> 9))*NL;
        float* S0 = S + ((size_t)b*8192 + gm0)*NL;
        float* S1 = S + ((size_t)b*8192 + gm1)*NL;
#pragma unroll
        for (int nt = 0; nt < 4; nt++) {
            int gn = n0 + wn*32 + nt*8 + c2_;
            float2 a2 = *(const float2*)&ad[gn];
            float2 o0, o1;
            o0.x = acc[mt][nt][0] + pb0 + a2.x;
            o0.y = acc[mt][nt][1] + pb0 + a2.y;
            o1.x = acc[mt][nt][2] + pb1 + a2.x;
            o1.y = acc[mt][nt][3] + pb1 + a2.y;
            *(float2*)&S0[gn] = o0;
            *(float2*)&S1[gn] = o1;
        }
    }
}

// ---------------- softmax (512) in place + fp16 copy ----------------
__global__ __launch_bounds__(128) void k_softmax(float* __restrict__ S)
{
    int row = blockIdx.x;
    float* p = S + (size_t)row * NL;
    int t = threadIdx.x;
    float x[4];
    float mx = -INFINITY;
#pragma unroll
    for (int i = 0; i < 4; i++) { x[i] = p[t + i*128]; mx = fmaxf(mx, x[i]); }
    __shared__ float smx[4], ssum[4];
#pragma unroll
    for (int o = 16; o > 0; o >>= 1) mx = fmaxf(mx, __shfl_xor_sync(0xffffffffu, mx, o));
    if ((t & 31) == 0) smx[t >> 5] = mx;
    __syncthreads();
    mx = fmaxf(fmaxf(smx[0], smx[1]), fmaxf(smx[2], smx[3]));
    float s = 0.f;
#pragma unroll
    for (int i = 0; i < 4; i++) { x[i] = expf(x[i] - mx); s += x[i]; }
#pragma unroll
    for (int o = 16; o > 0; o >>= 1) s += __shfl_xor_sync(0xffffffffu, s, o);
    if ((t & 31) == 0) ssum[t >> 5] = s;
    __syncthreads();
    s = ssum[0] + ssum[1] + ssum[2] + ssum[3];
    float inv = 1.0f / s;
    size_t rb = (size_t)row * NL;
#pragma unroll
    for (int i = 0; i < 4; i++) {
        float y = x[i] * inv;
        p[t + i*128] = y;
        g_Sf[rb + t + i*128] = __float2half_rn(y);
    }
}

// ---------------- FUSED: out = ((attn@c1)*U) @ W^T + attn @ D^T -----------------
// grid (8 m-tiles of 64, 64 bh), 256 threads. attn [64x512] resident in smem.
__global__ __launch_bounds__(256, 1) void k_av_out(
    const float* __restrict__ U, float* __restrict__ Out)
{
    extern __shared__ char smraw[];
    u32 uSm = s2u(smraw);
    int t = threadIdx.x, lane = t & 31, wid = t >> 5;
    int m0 = blockIdx.x * 64;
    int bh = blockIdx.y, b = bh >> 4, h = bh & 15;
    size_t grow = (size_t)bh*NT + m0;

    const __half* Sp = g_Sf + grow*NL;
    const __half* Dp = g_Df + (size_t)bh*E_*NL;
    const __half* Tp = g_tf + (size_t)b*P_*NL;
    const __nv_bfloat16* WhP = g_Wh + (size_t)h*E_*P_;
    const __nv_bfloat16* WlP = g_Wl + (size_t)h*E_*P_;
    const float* Up = U + grow*P_;

    // 2x4 layout (Gacc: tile 64m x 128p)
    int wm = wid >> 2, wn = wid & 3;
    int arow  = wm*32 + (lane & 15);
    int acolo = (lane >> 4) * 8;
    int brow  = wn*32 + (lane & 7) + ((lane >> 4) * 8);
    int bcolo = ((lane >> 3) & 1) * 8;
    // 4x2 layout (out: tile 64m x 64e)
    int wm2 = wid >> 1, wn2 = wid & 1;
    int arow2 = wm2*16 + (lane & 15);
    int brow2 = wn2*32 + (lane & 7) + ((lane >> 4) * 8);

    float oacc[4][4] = {};

    // ---------- Phase A: resident attn + out2 = attn @ D^T ----------
    {
        // attn: 8 chunks of [64 x 64]
#pragma unroll
        for (int ch = 0; ch < 8; ch++)
#pragma unroll
            for (int i = 0; i < 2; i++) {
                int q = t + i*256;
                int row = q >> 3, cg = (q & 7) * 8;
                CPA(uSm + ATT_OFF + ch*CH + (u32)(row*SAS + cg)*2,
                    Sp + (size_t)row*NL + ch*64 + cg);
            }
        auto load_D = [&](int ch, int buf) {
#pragma unroll
            for (int i = 0; i < 2; i++) {
                int q = t + i*256;
                int row = q >> 3, cg = (q & 7) * 8;
                CPA(uSm + C1_OFF + buf*CH + (u32)(row*SAS + cg)*2,
                    Dp + (size_t)row*NL + ch*64 + cg);
            }
        };
        load_D(0, 0); CP_COMMIT();
        load_D(1, 1); CP_COMMIT();
        for (int ch = 0; ch < 8; ch++) {
            if (ch < 7) { CP_WAIT(1); } else { CP_WAIT(0); }
            __syncthreads();
            if (ch + 2 < 8) { load_D(ch+2, (ch+2)%3); CP_COMMIT(); }
            u32 uA = uSm + ATT_OFF + ch*CH;
            u32 uD = uSm + C1_OFF + (ch%3)*CH;
#pragma unroll
            for (int ks = 0; ks < 4; ks++) {
                int k = ks * 16;
                u32 aF[4], bF[4][2];
                ldsm4(aF[0], aF[1], aF[2], aF[3], uA + (u32)((arow2*SAS + k + acolo)*2));
#pragma unroll
                for (int pr = 0; pr < 2; pr++)
                    ldsm4(bF[2*pr][0], bF[2*pr][1], bF[2*pr+1][0], bF[2*pr+1][1],
                          uD + (u32)(((brow2 + pr*16)*SAS + k + bcolo)*2));
#pragma unroll
                for (int nt = 0; nt < 4; nt++)
                    mma_f16(oacc[nt], aF, bF[nt]);
            }
        }
        __syncthreads();   // D ring free; phase B reuses C1 region
    }

    // ---------- Phase B: per p0 tile: Gtile = attn@c1; out += Gtile@W^T ----------
    auto load_W = [&](int p0) {
#pragma unroll
        for (int i = 0; i < 2; i++) {
            int q = t + i*256;
            int row = q >> 3, cg = (q & 7) * 8;
            u32 doff = (u32)(row*SAS + cg)*2;
            size_t so = (size_t)row * P_ + p0*128 + cg;
            CPA(uSm + WS_OFF + 0*CH + doff, WhP + so);
            CPA(uSm + WS_OFF + 1*CH + doff, WhP + so + 64);
            CPA(uSm + WS_OFF + 2*CH + doff, WlP + so);
            CPA(uSm + WS_OFF + 3*CH + doff, WlP + so + 64);
        }
    };
    auto load_c1 = [&](int p0, int ch, int buf) {
#pragma unroll
        for (int i = 0; i < 4; i++) {
            int q = t + i*256;
            int row = q >> 3, cg = (q & 7) * 8;   // row 0..127
            CPA(uSm + C1_OFF + buf*C1CH + (u32)(row*SAS + cg)*2,
                Tp + (size_t)(p0*128 + row)*NL + ch*64 + cg);
        }
    };

    int r = lane >> 2, c2_ = (lane & 3) * 2;

#pragma unroll 1
    for (int p0 = 0; p0 < 8; p0++) {
        load_W(p0); load_c1(p0, 0, 0); CP_COMMIT();
        load_c1(p0, 1, 1); CP_COMMIT();
        float gacc[2][4][4] = {};
        for (int ch = 0; ch < 8; ch++) {
            if (ch < 7) { CP_WAIT(1); } else { CP_WAIT(0); }
            __syncthreads();
            if (ch + 2 < 8) { load_c1(p0, ch+2, (ch+2)%3); CP_COMMIT(); }
            u32 uA = uSm + ATT_OFF + ch*CH;
            u32 uB = uSm + C1_OFF + (ch%3)*C1CH;
#pragma unroll
            for (int ks = 0; ks < 4; ks++) {
                int k = ks * 16;
                u32 aF[2][4], bF[4][2];
#pragma unroll
                for (int mt = 0; mt < 2; mt++)
                    ldsm4(aF[mt][0], aF[mt][1], aF[mt][2], aF[mt][3],
                          uA + (u32)(((arow + mt*16)*SAS + k + acolo)*2));
#pragma unroll
                for (int pr = 0; pr < 2; pr++)
                    ldsm4(bF[2*pr][0], bF[2*pr][1], bF[2*pr+1][0], bF[2*pr+1][1],
                          uB + (u32)(((brow + pr*16)*SAS + k + bcolo)*2));
#pragma unroll
                for (int mt = 0; mt < 2; mt++)
#pragma unroll
                    for (int nt = 0; nt < 4; nt++)
                        mma_f16(gacc[mt][nt], aF[mt], bF[nt]);
            }
        }
        // epilogue: * U, split to Gtile smem (bf16 hi/lo)
#pragma unroll
        for (int mt = 0; mt < 2; mt++) {
            int rl0 = wm*32 + mt*16 + r;
            int rl1 = rl0 + 8;
            const float* U0 = Up + (size_t)rl0*P_ + p0*128;
            const float* U1 = Up + (size_t)rl1*P_ + p0*128;
#pragma unroll
            for (int nt = 0; nt < 4; nt++) {
                int cl = wn*32 + nt*8 + c2_;
                int kc = cl >> 6, wc = cl & 63;
                float2 u0 = *(const float2*)&U0[cl];
                float2 u1 = *(const float2*)&U1[cl];
                float gx, gy;
                __nv_bfloat16 h0, l0, h1, l1;
                gx = gacc[mt][nt][0]*u0.x; gy = gacc[mt][nt][1]*u0.y;
                splitbf(gx, h0, l0); splitbf(gy, h1, l1);
                *(__nv_bfloat162*)(smraw + GT_OFF + kc*CH + (rl0*SAS + wc)*2) = __nv_bfloat162(h0, h1);
                *(__nv_bfloat162*)(smraw + GT_OFF + (2+kc)*CH + (rl0*SAS + wc)*2) = __nv_bfloat162(l0, l1);
                gx = gacc[mt][nt][2]*u1.x; gy = gacc[mt][nt][3]*u1.y;
                splitbf(gx, h0, l0); splitbf(gy, h1, l1);
                *(__nv_bfloat162*)(smraw + GT_OFF + kc*CH + (rl1*SAS + wc)*2) = __nv_bfloat162(h0, h1);
                *(__nv_bfloat162*)(smraw + GT_OFF + (2+kc)*CH + (rl1*SAS + wc)*2) = __nv_bfloat162(l0, l1);
            }
        }
        __syncthreads();
        // out1 MMA: A = Gtile [64m x 128k], B = W [64e x 128k], bf16 3-product
#pragma unroll
        for (int kc = 0; kc < 2; kc++) {
            u32 uGh = uSm + GT_OFF + kc*CH,       uGl = uGh + 2*CH;
            u32 uWh = uSm + WS_OFF + kc*CH,       uWl = uWh + 2*CH;
#pragma unroll
            for (int ks = 0; ks < 4; ks++) {
                int k = ks * 16;
                u32 aH[4], aL[4], bH[4][2], bL[4][2];
                ldsm4(aH[0], aH[1], aH[2], aH[3], uGh + (u32)((arow2*SAS + k + acolo)*2));
                ldsm4(aL[0], aL[1], aL[2], aL[3], uGl + (u32)((arow2*SAS + k + acolo)*2));
#pragma unroll
                for (int pr = 0; pr < 2; pr++) {
                    u32 off = (u32)(((brow2 + pr*16)*SAS + k + bcolo)*2);
                    ldsm4(bH[2*pr][0], bH[2*pr][1], bH[2*pr+1][0], bH[2*pr+1][1], uWh + off);
                    ldsm4(bL[2*pr][0], bL[2*pr][1], bL[2*pr+1][0], bL[2*pr+1][1], uWl + off);
                }
#pragma unroll
                for (int nt = 0; nt < 4; nt++) {
                    mma_bf16(oacc[nt], aH, bH[nt]);
                    mma_bf16(oacc[nt], aH, bL[nt]);
                    mma_bf16(oacc[nt], aL, bH[nt]);
                }
            }
        }
        __syncthreads();   // free Gtile + W for next p0
    }

    // final store
    float* O0 = Out + (grow + wm2*16 + r)*E_;
    float* O1 = O0 + 8*(size_t)E_;
#pragma unroll
    for (int nt = 0; nt < 4; nt++) {
        int ge = wn2*32 + nt*8 + c2_;
        float2 o0, o1;
        o0.x = oacc[nt][0]; o0.y = oacc[nt][1];
        o1.x = oacc[nt][2]; o1.y = oacc[nt][3];
        *(float2*)&O0[ge] = o0;
        *(float2*)&O1[ge] = o1;
    }
}

// ---------------- launch ----------------
extern "C" void kernel_launch(void* const* d_in, const int* in_sizes, int n_in,
                              void* d_out, int out_size)
{
    const float* pu     = (const float*)d_in[0];  // [B,H,Nt,P]
    const float* pb     = (const float*)d_in[1];  // [B,H,Nt,1]
    const float* mu     = (const float*)d_in[2];  // [B,Nl,P]
    const float* logvar = (const float*)d_in[3];  // [B,Nl,P]
    const float* pi     = (const float*)d_in[4];  // [B,Nl,1]
    const float* wv     = (const float*)d_in[5];  // [H,E,P]
    const float* bvv    = (const float*)d_in[6];  // [H,E,Nl]
    const unsigned char* mask = (const unsigned char*)d_in[7]; // [B*H,1,Nl]

    float* out  = (float*)d_out;                  // [BH,Nt,E]
    float* attn = out + (size_t)BH*NT*E_;         // [BH,Nt,Nl]

    __nv_bfloat16 *Uh, *Ul, *Wh, *Wl;
    cudaGetSymbolAddress((void**)&Uh, g_Uh);
    cudaGetSymbolAddress((void**)&Ul, g_Ul);
    cudaGetSymbolAddress((void**)&Wh, g_Wh);
    cudaGetSymbolAddress((void**)&Wl, g_Wl);

    const int SM_SCORES = 3 * 4 * TILE_B;                  // 221184 B
    const int SM_D      = 3 * (2 * TILE_B + 2 * HTILE_B);  // 165888 B
    cudaFuncSetAttribute(k_scores_mma, cudaFuncAttributeMaxDynamicSharedMemorySize, SM_SCORES);
    cudaFuncSetAttribute(k_D_mma,      cudaFuncAttributeMaxDynamicSharedMemorySize, SM_D);
    cudaFuncSetAttribute(k_av_out,     cudaFuncAttributeMaxDynamicSharedMemorySize, SM_FUSED);

    k_prep      <<<dim3(NL, B_),     256>>>(mu, logvar, pi, mask);
    k_split     <<<32768,            256>>>(pu, Uh, Ul);
    k_split     <<<1024,             256>>>(wv, Wh, Wl);
    k_D_mma     <<<dim3(NL/128, BH), 256, SM_D>>>(bvv);
    k_scores_mma<<<dim3(4, 64, B_),  256, SM_SCORES>>>(pb, attn);
    k_softmax   <<<BH*NT,            128>>>(attn);
    k_av_out    <<<dim3(8, BH),      256, SM_FUSED>>>(pu, out);
}

// round 17
// speedup vs baseline: 1.0956x; 1.0162x over previous
#include <cuda_runtime.h>
#include <cuda_bf16.h>
#include <cuda_fp16.h>
#include <math.h>
#include <stdint.h>

#define B_  4
#define H_  16
#define NT  512
#define NL  512
#define E_  64
#define P_  1024
#define BH  (B_*H_)
#define PRIOR 8.0f

typedef unsigned int u32;

// ---------------- scratch (device globals) ----------------
__device__ __nv_bfloat16 g_Uh[(size_t)B_*8192*P_];  // U split hi  [b*8192+m][p]
__device__ __nv_bfloat16 g_Ul[(size_t)B_*8192*P_];
__device__ __nv_bfloat16 g_rh[B_*NL*P_];            // r = mu/bv hi [b][n][p]
__device__ __nv_bfloat16 g_rl[B_*NL*P_];
__device__ __half        g_tf[B_*P_*NL];            // c1^T fp16 [b][p][n]
__device__ __half        g_Sf[(size_t)BH*NT*NL];    // attn fp16 [bh*Nt+m][n]
__device__ __nv_bfloat16 g_Wh[H_*E_*P_];            // w_v split hi [h*E+e][p] (1024 x 1024)
__device__ __nv_bfloat16 g_Wl[H_*E_*P_];
__device__ __half        g_Df[(size_t)BH*E_*NL];    // D^T fp16 [bh][e][n]
__device__ float g_add[BH*NL];

// ---------------- helpers ----------------
__device__ __forceinline__ u32 s2u(const void* p) {
    u32 a; asm("{ .reg .u64 t; cvta.to.shared.u64 t, %1; cvt.u32.u64 %0, t; }" : "=r"(a) : "l"(p));
    return a;
}
__device__ __forceinline__ void ldsm4(u32& r0, u32& r1, u32& r2, u32& r3, u32 a) {
    asm volatile("ldmatrix.sync.aligned.m8n8.x4.shared.b16 {%0,%1,%2,%3}, [%4];"
        : "=r"(r0), "=r"(r1), "=r"(r2), "=r"(r3) : "r"(a));
}
__device__ __forceinline__ void mma_bf16(float* c, const u32* a, const u32* b) {
    asm volatile("mma.sync.aligned.m16n8k16.row.col.f32.bf16.bf16.f32 "
        "{%0,%1,%2,%3}, {%4,%5,%6,%7}, {%8,%9}, {%0,%1,%2,%3};"
        : "+f"(c[0]), "+f"(c[1]), "+f"(c[2]), "+f"(c[3])
        : "r"(a[0]), "r"(a[1]), "r"(a[2]), "r"(a[3]), "r"(b[0]), "r"(b[1]));
}
__device__ __forceinline__ void mma_f16(float* c, const u32* a, const u32* b) {
    asm volatile("mma.sync.aligned.m16n8k16.row.col.f32.f16.f16.f32 "
        "{%0,%1,%2,%3}, {%4,%5,%6,%7}, {%8,%9}, {%0,%1,%2,%3};"
        : "+f"(c[0]), "+f"(c[1]), "+f"(c[2]), "+f"(c[3])
        : "r"(a[0]), "r"(a[1]), "r"(a[2]), "r"(a[3]), "r"(b[0]), "r"(b[1]));
}
__device__ __forceinline__ void splitbf(float x, __nv_bfloat16& h, __nv_bfloat16& l) {
    h = __float2bfloat16_rn(x);
    l = __float2bfloat16_rn(x - __bfloat162float(h));
}
#define CPA(s, g)   asm volatile("cp.async.cg.shared.global [%0], [%1], 16;" :: "r"(s), "l"(g) : "memory")
#define CP_COMMIT() asm volatile("cp.async.commit_group;" ::: "memory")
#define CP_WAIT(n)  asm volatile("cp.async.wait_group %0;" :: "n"(n) : "memory")

#define SAS     72                   // padded smem stride (elems)
#define TILE_E  (128*SAS)            // elems per 128-row tile
#define TILE_B  (TILE_E*2)           // bytes

// fused kernel smem layout (all 64-col chunks, stride SAS)
#define CH      (64*SAS*2)           // 9216 B : [64 rows x 64 cols] fp16/bf16
#define C1CH    (128*SAS*2)          // 18432 B: [128 rows x 64 cols]
#define ATT_OFF 0                    // 8 x CH  = 73728 (attn resident)
#define C1_OFF  (8*CH)               // 3 x C1CH = 55296 (c1 ring; D ring reuses)
#define WS_OFF  (C1_OFF + 3*C1CH)    // 4 x CH = 36864 (Wh c0,c1, Wl c0,c1)
#define GT_OFF  (WS_OFF + 4*CH)      // 4 x CH = 36864 (Gh c0,c1, Gl c0,c1)
#define SM_FUSED (GT_OFF + 4*CH)     // 202752 B

// ---------------- K0: per-(b,n) precompute + splits + reductions ----------------
__global__ __launch_bounds__(256) void k_prep(
    const float* __restrict__ mu, const float* __restrict__ logvar,
    const float* __restrict__ pi, const unsigned char* __restrict__ mask)
{
    int n = blockIdx.x, b = blockIdx.y;
    int base = (b*NL + n)*P_;
    int t = threadIdx.x;
    float s2 = 0.f, s3 = 0.f;
#pragma unroll
    for (int i = 0; i < 4; i++) {
        int p = t + i*256;
        float m  = mu[base+p];
        float v  = expf(logvar[base+p]);
        float bv = v + PRIOR;
        float inv = 1.0f / bv;
        float r  = m * inv;
        float c1 = v * inv;
        __nv_bfloat16 h, l;
        splitbf(r, h, l);
        g_rh[base+p] = h; g_rl[base+p] = l;
        g_tf[((size_t)b*P_ + p)*NL + n] = __float2half_rn(c1);
        s2 += m * m * inv;
        s3 += logf(bv);
    }
    __shared__ float red2[8], red3[8];
#pragma unroll
    for (int o = 16; o > 0; o >>= 1) {
        s2 += __shfl_down_sync(0xffffffffu, s2, o);
        s3 += __shfl_down_sync(0xffffffffu, s3, o);
    }
    if ((t & 31) == 0) { red2[t>>5] = s2; red3[t>>5] = s3; }
    __syncthreads();
    __shared__ float sbase;
    if (t == 0) {
        float a2 = 0.f, a3 = 0.f;
        for (int i = 0; i < 8; i++) { a2 += red2[i]; a3 += red3[i]; }
        float piv = pi[b*NL + n];
        float pc  = fmaxf(piv, 1.17549435e-38f);
        sbase = logf(pc) - 0.5f*a2 - 0.5f*a3;
    }
    __syncthreads();
    if (t < H_) {
        float piv = pi[b*NL + n];
        bool msk = (mask[(b*H_ + t)*NL + n] != 0) || (piv <= 0.f);
        g_add[(b*H_ + t)*NL + n] = msk ? -INFINITY : sbase;
    }
}

// ---------------- generic fp32 -> bf16 hi/lo splitter ----------------
__global__ __launch_bounds__(256) void k_split(
    const float* __restrict__ X, __nv_bfloat16* __restrict__ Xh,
    __nv_bfloat16* __restrict__ Xl)
{
    size_t i = ((size_t)blockIdx.x * 256 + threadIdx.x) * 4;
    float4 v = *(const float4*)(X + i);
    __nv_bfloat16 h[4], l[4];
    splitbf(v.x, h[0], l[0]); splitbf(v.y, h[1], l[1]);
    splitbf(v.z, h[2], l[2]); splitbf(v.w, h[3], l[3]);
    uint2 uh, ul;
    uh.x = ((u32)__bfloat16_as_ushort(h[1]) << 16) | __bfloat16_as_ushort(h[0]);
    uh.y = ((u32)__bfloat16_as_ushort(h[3]) << 16) | __bfloat16_as_ushort(h[2]);
    ul.x = ((u32)__bfloat16_as_ushort(l[1]) << 16) | __bfloat16_as_ushort(l[0]);
    ul.y = ((u32)__bfloat16_as_ushort(l[3]) << 16) | __bfloat16_as_ushort(l[2]);
    *(uint2*)&Xh[i] = uh;
    *(uint2*)&Xl[i] = ul;
}

// ---------------- shared 128x128x1024 bf16 3-product mainloop -------------------
__device__ __forceinline__ void gemm3_mainloop(
    u32 uSm, int t,
    const __nv_bfloat16* __restrict__ Ah, const __nv_bfloat16* __restrict__ Al,
    const __nv_bfloat16* __restrict__ Bh, const __nv_bfloat16* __restrict__ Bl,
    int arow, int acolo, int brow, int bcolo,
    float acc[4][4][4])
{
    const u32 BUFB = 4*TILE_B;
    auto load_chunk = [&](int c, int buf) {
        u32 sbb = uSm + (u32)buf * BUFB;
        int k0 = c * 64;
#pragma unroll
        for (int i = 0; i < 4; i++) {
            int q = t + i*256;
            int row = q >> 3, cc = (q & 7) * 8;
            u32 doff = (u32)(row*SAS + cc) * 2;
            size_t so = (size_t)row * P_ + k0 + cc;
            CPA(sbb + 0*TILE_B + doff, Ah + so);
            CPA(sbb + 1*TILE_B + doff, Al + so);
            CPA(sbb + 2*TILE_B + doff, Bh + so);
            CPA(sbb + 3*TILE_B + doff, Bl + so);
        }
    };

    load_chunk(0, 0); CP_COMMIT();
    load_chunk(1, 1); CP_COMMIT();
    int bufc = 0, bufn = 2;
    for (int c = 0; c < 16; c++) {
        if (c + 1 < 16) { CP_WAIT(1); } else { CP_WAIT(0); }
        __syncthreads();
        if (c + 2 < 16) { load_chunk(c+2, bufn); CP_COMMIT(); }
        u32 u0 = uSm + (u32)bufc * BUFB;
        u32 uAh = u0, uAl = u0 + TILE_B, uBh = u0 + 2*TILE_B, uBl = u0 + 3*TILE_B;
#pragma unroll
        for (int ks = 0; ks < 4; ks++) {
            int k = ks * 16;
            u32 aH[4][4], aL[4][4], bH[4][2], bL[4][2];
#pragma unroll
            for (int mt = 0; mt < 4; mt++) {
                u32 off = (u32)(((arow + mt*16)*SAS + k + acolo) * 2);
                ldsm4(aH[mt][0], aH[mt][1], aH[mt][2], aH[mt][3], uAh + off);
                ldsm4(aL[mt][0], aL[mt][1], aL[mt][2], aL[mt][3], uAl + off);
            }
#pragma unroll
            for (int pr = 0; pr < 2; pr++) {
                u32 off = (u32)(((brow + pr*16)*SAS + k + bcolo) * 2);
                ldsm4(bH[2*pr][0], bH[2*pr][1], bH[2*pr+1][0], bH[2*pr+1][1], uBh + off);
                ldsm4(bL[2*pr][0], bL[2*pr][1], bL[2*pr+1][0], bL[2*pr+1][1], uBl + off);
            }
#pragma unroll
            for (int mt = 0; mt < 4; mt++)
#pragma unroll
                for (int nt = 0; nt < 4; nt++) {
                    mma_bf16(acc[mt][nt], aH[mt], bH[nt]);
                    mma_bf16(acc[mt][nt], aH[mt], bL[nt]);
                    mma_bf16(acc[mt][nt], aL[mt], bH[nt]);
                }
        }
        bufc = (bufc + 1 == 3) ? 0 : bufc + 1;
        bufn = (bufn + 1 == 3) ? 0 : bufn + 1;
    }
}

// ---------------- K1 unified: scores tiles (x<4) + D tiles (x==4) ---------------
// grid (5, 64, B_). scores: n0=x*128, m0=y*128, b=z.
// D: y<32 only; b=z, n-tile=(y&3), e-tile=(y>>2) over Wall rows (1024).
__global__ __launch_bounds__(256, 1) void k_scores_D(
    const float* __restrict__ pb, float* __restrict__ S,
    const float* __restrict__ bvv)
{
    extern __shared__ char smraw[];
    u32 uSm = s2u(smraw);
    int t = threadIdx.x, lane = t & 31, wid = t >> 5;
    int wm = wid >> 2, wn = wid & 3;

    int arow  = wm*64 + (lane & 15);
    int acolo = (lane >> 4) * 8;
    int brow  = wn*32 + (lane & 7) + ((lane >> 4) * 8);
    int bcolo = ((lane >> 3) & 1) * 8;
    int r = lane >> 2, c2_ = (lane & 3) * 2;

    float acc[4][4][4] = {};

    if (blockIdx.x < 4) {
        // ----- scores path -----
        int n0 = blockIdx.x * 128, m0 = blockIdx.y * 128, b = blockIdx.z;
        gemm3_mainloop(uSm, t,
            g_Uh + ((size_t)b*8192 + m0)*P_, g_Ul + ((size_t)b*8192 + m0)*P_,
            g_rh + ((size_t)b*NL   + n0)*P_, g_rl + ((size_t)b*NL   + n0)*P_,
            arow, acolo, brow, bcolo, acc);

#pragma unroll
        for (int mt = 0; mt < 4; mt++) {
            int gm0 = m0 + wm*64 + mt*16 + r;
            int gm1 = gm0 + 8;
            float pb0 = pb[(size_t)b*8192 + gm0];
            float pb1 = pb[(size_t)b*8192 + gm1];
            const float* ad = g_add + ((size_t)(b*H_) + (gm0 >> 9))*NL;
            float* S0 = S + ((size_t)b*8192 + gm0)*NL;
            float* S1 = S + ((size_t)b*8192 + gm1)*NL;
#pragma unroll
            for (int nt = 0; nt < 4; nt++) {
                int gn = n0 + wn*32 + nt*8 + c2_;
                float2 a2 = *(const float2*)&ad[gn];
                float2 o0, o1;
                o0.x = acc[mt][nt][0] + pb0 + a2.x;
                o0.y = acc[mt][nt][1] + pb0 + a2.y;
                o1.x = acc[mt][nt][2] + pb1 + a2.x;
                o1.y = acc[mt][nt][3] + pb1 + a2.y;
                *(float2*)&S0[gn] = o0;
                *(float2*)&S1[gn] = o1;
            }
        }
    } else {
        // ----- D path: D^T = 8*(r @ Wall^T) + b_v^T -----
        if (blockIdx.y >= 32) return;
        int b  = blockIdx.z;
        int n0 = (blockIdx.y & 3) * 128;     // over NL
        int e0 = (blockIdx.y >> 2) * 128;    // over Wall rows (h*64+e)
        gemm3_mainloop(uSm, t,
            g_rh + ((size_t)b*NL + n0)*P_, g_rl + ((size_t)b*NL + n0)*P_,
            g_Wh + (size_t)e0*P_,          g_Wl + (size_t)e0*P_,
            arow, acolo, brow, bcolo, acc);

#pragma unroll
        for (int mt = 0; mt < 4; mt++) {
            int gn0 = n0 + wm*64 + mt*16 + r;   // n index
            int gn1 = gn0 + 8;
#pragma unroll
            for (int nt = 0; nt < 4; nt++) {
#pragma unroll
                for (int j = 0; j < 2; j++) {
                    int we = e0 + wn*32 + nt*8 + c2_ + j;   // Wall row
                    int h = we >> 6, e = we & 63;
                    size_t be = ((size_t)h*E_ + e)*NL;
                    size_t de = ((size_t)(b*H_ + h)*E_ + e)*NL;
                    g_Df[de + gn0] = __float2half_rn(PRIOR*acc[mt][nt][0 + j] + bvv[be + gn0]);
                    g_Df[de + gn1] = __float2half_rn(PRIOR*acc[mt][nt][2 + j] + bvv[be + gn1]);
                }
            }
        }
    }
}

// ---------------- softmax (512) in place + fp16 copy ----------------
__global__ __launch_bounds__(128) void k_softmax(float* __restrict__ S)
{
    int row = blockIdx.x;
    float* p = S + (size_t)row * NL;
    int t = threadIdx.x;
    float x[4];
    float mx = -INFINITY;
#pragma unroll
    for (int i = 0; i < 4; i++) { x[i] = p[t + i*128]; mx = fmaxf(mx, x[i]); }
    __shared__ float smx[4], ssum[4];
#pragma unroll
    for (int o = 16; o > 0; o >>= 1) mx = fmaxf(mx, __shfl_xor_sync(0xffffffffu, mx, o));
    if ((t & 31) == 0) smx[t >> 5] = mx;
    __syncthreads();
    mx = fmaxf(fmaxf(smx[0], smx[1]), fmaxf(smx[2], smx[3]));
    float s = 0.f;
#pragma unroll
    for (int i = 0; i < 4; i++) { x[i] = expf(x[i] - mx); s += x[i]; }
#pragma unroll
    for (int o = 16; o > 0; o >>= 1) s += __shfl_xor_sync(0xffffffffu, s, o);
    if ((t & 31) == 0) ssum[t >> 5] = s;
    __syncthreads();
    s = ssum[0] + ssum[1] + ssum[2] + ssum[3];
    float inv = 1.0f / s;
    size_t rb = (size_t)row * NL;
#pragma unroll
    for (int i = 0; i < 4; i++) {
        float y = x[i] * inv;
        p[t + i*128] = y;
        g_Sf[rb + t + i*128] = __float2half_rn(y);
    }
}

// ---------------- FUSED: out = ((attn@c1)*U) @ W^T + attn @ D^T -----------------
__global__ __launch_bounds__(256, 1) void k_av_out(
    const float* __restrict__ U, float* __restrict__ Out)
{
    extern __shared__ char smraw[];
    u32 uSm = s2u(smraw);
    int t = threadIdx.x, lane = t & 31, wid = t >> 5;
    int m0 = blockIdx.x * 64;
    int bh = blockIdx.y, b = bh >> 4, h = bh & 15;
    size_t grow = (size_t)bh*NT + m0;

    const __half* Sp = g_Sf + grow*NL;
    const __half* Dp = g_Df + (size_t)bh*E_*NL;
    const __half* Tp = g_tf + (size_t)b*P_*NL;
    const __nv_bfloat16* WhP = g_Wh + (size_t)h*E_*P_;
    const __nv_bfloat16* WlP = g_Wl + (size_t)h*E_*P_;
    const float* Up = U + grow*P_;

    int wm = wid >> 2, wn = wid & 3;
    int arow  = wm*32 + (lane & 15);
    int acolo = (lane >> 4) * 8;
    int brow  = wn*32 + (lane & 7) + ((lane >> 4) * 8);
    int bcolo = ((lane >> 3) & 1) * 8;
    int wm2 = wid >> 1, wn2 = wid & 1;
    int arow2 = wm2*16 + (lane & 15);
    int brow2 = wn2*32 + (lane & 7) + ((lane >> 4) * 8);

    float oacc[4][4] = {};

    // ---------- Phase A: resident attn + out2 = attn @ D^T ----------
    {
#pragma unroll
        for (int ch = 0; ch < 8; ch++)
#pragma unroll
            for (int i = 0; i < 2; i++) {
                int q = t + i*256;
                int row = q >> 3, cg = (q & 7) * 8;
                CPA(uSm + ATT_OFF + ch*CH + (u32)(row*SAS + cg)*2,
                    Sp + (size_t)row*NL + ch*64 + cg);
            }
        auto load_D = [&](int ch, int buf) {
#pragma unroll
            for (int i = 0; i < 2; i++) {
                int q = t + i*256;
                int row = q >> 3, cg = (q & 7) * 8;
                CPA(uSm + C1_OFF + buf*CH + (u32)(row*SAS + cg)*2,
                    Dp + (size_t)row*NL + ch*64 + cg);
            }
        };
        load_D(0, 0); CP_COMMIT();
        load_D(1, 1); CP_COMMIT();
        for (int ch = 0; ch < 8; ch++) {
            if (ch < 7) { CP_WAIT(1); } else { CP_WAIT(0); }
            __syncthreads();
            if (ch + 2 < 8) { load_D(ch+2, (ch+2)%3); CP_COMMIT(); }
            u32 uA = uSm + ATT_OFF + ch*CH;
            u32 uD = uSm + C1_OFF + (ch%3)*CH;
#pragma unroll
            for (int ks = 0; ks < 4; ks++) {
                int k = ks * 16;
                u32 aF[4], bF[4][2];
                ldsm4(aF[0], aF[1], aF[2], aF[3], uA + (u32)((arow2*SAS + k + acolo)*2));
#pragma unroll
                for (int pr = 0; pr < 2; pr++)
                    ldsm4(bF[2*pr][0], bF[2*pr][1], bF[2*pr+1][0], bF[2*pr+1][1],
                          uD + (u32)(((brow2 + pr*16)*SAS + k + bcolo)*2));
#pragma unroll
                for (int nt = 0; nt < 4; nt++)
                    mma_f16(oacc[nt], aF, bF[nt]);
            }
        }
        __syncthreads();
    }

    // ---------- Phase B: per p0: Gtile = attn@c1; out += Gtile@W^T ----------
    auto load_W = [&](int p0) {
#pragma unroll
        for (int i = 0; i < 2; i++) {
            int q = t + i*256;
            int row = q >> 3, cg = (q & 7) * 8;
            u32 doff = (u32)(row*SAS + cg)*2;
            size_t so = (size_t)row * P_ + p0*128 + cg;
            CPA(uSm + WS_OFF + 0*CH + doff, WhP + so);
            CPA(uSm + WS_OFF + 1*CH + doff, WhP + so + 64);
            CPA(uSm + WS_OFF + 2*CH + doff, WlP + so);
            CPA(uSm + WS_OFF + 3*CH + doff, WlP + so + 64);
        }
    };
    auto load_c1 = [&](int p0, int ch, int buf) {
#pragma unroll
        for (int i = 0; i < 4; i++) {
            int q = t + i*256;
            int row = q >> 3, cg = (q & 7) * 8;
            CPA(uSm + C1_OFF + buf*C1CH + (u32)(row*SAS + cg)*2,
                Tp + (size_t)(p0*128 + row)*NL + ch*64 + cg);
        }
    };

    int r = lane >> 2, c2_ = (lane & 3) * 2;

#pragma unroll 1
    for (int p0 = 0; p0 < 8; p0++) {
        load_W(p0); load_c1(p0, 0, 0); CP_COMMIT();
        load_c1(p0, 1, 1); CP_COMMIT();
        float gacc[2][4][4] = {};
        for (int ch = 0; ch < 8; ch++) {
            if (ch < 7) { CP_WAIT(1); } else { CP_WAIT(0); }
            __syncthreads();
            if (ch + 2 < 8) { load_c1(p0, ch+2, (ch+2)%3); CP_COMMIT(); }
            u32 uA = uSm + ATT_OFF + ch*CH;
            u32 uB = uSm + C1_OFF + (ch%3)*C1CH;
#pragma unroll
            for (int ks = 0; ks < 4; ks++) {
                int k = ks * 16;
                u32 aF[2][4], bF[4][2];
#pragma unroll
                for (int mt = 0; mt < 2; mt++)
                    ldsm4(aF[mt][0], aF[mt][1], aF[mt][2], aF[mt][3],
                          uA + (u32)(((arow + mt*16)*SAS + k + acolo)*2));
#pragma unroll
                for (int pr = 0; pr < 2; pr++)
                    ldsm4(bF[2*pr][0], bF[2*pr][1], bF[2*pr+1][0], bF[2*pr+1][1],
                          uB + (u32)(((brow + pr*16)*SAS + k + bcolo)*2));
#pragma unroll
                for (int mt = 0; mt < 2; mt++)
#pragma unroll
                    for (int nt = 0; nt < 4; nt++)
                        mma_f16(gacc[mt][nt], aF[mt], bF[nt]);
            }
        }
#pragma unroll
        for (int mt = 0; mt < 2; mt++) {
            int rl0 = wm*32 + mt*16 + r;
            int rl1 = rl0 + 8;
            const float* U0 = Up + (size_t)rl0*P_ + p0*128;
            const float* U1 = Up + (size_t)rl1*P_ + p0*128;
#pragma unroll
            for (int nt = 0; nt < 4; nt++) {
                int cl = wn*32 + nt*8 + c2_;
                int kc = cl >> 6, wc = cl & 63;
                float2 u0 = *(const float2*)&U0[cl];
                float2 u1 = *(const float2*)&U1[cl];
                float gx, gy;
                __nv_bfloat16 h0, l0, h1, l1;
                gx = gacc[mt][nt][0]*u0.x; gy = gacc[mt][nt][1]*u0.y;
                splitbf(gx, h0, l0); splitbf(gy, h1, l1);
                *(__nv_bfloat162*)(smraw + GT_OFF + kc*CH + (rl0*SAS + wc)*2) = __nv_bfloat162(h0, h1);
                *(__nv_bfloat162*)(smraw + GT_OFF + (2+kc)*CH + (rl0*SAS + wc)*2) = __nv_bfloat162(l0, l1);
                gx = gacc[mt][nt][2]*u1.x; gy = gacc[mt][nt][3]*u1.y;
                splitbf(gx, h0, l0); splitbf(gy, h1, l1);
                *(__nv_bfloat162*)(smraw + GT_OFF + kc*CH + (rl1*SAS + wc)*2) = __nv_bfloat162(h0, h1);
                *(__nv_bfloat162*)(smraw + GT_OFF + (2+kc)*CH + (rl1*SAS + wc)*2) = __nv_bfloat162(l0, l1);
            }
        }
        __syncthreads();
#pragma unroll
        for (int kc = 0; kc < 2; kc++) {
            u32 uGh = uSm + GT_OFF + kc*CH,  uGl = uGh + 2*CH;
            u32 uWh = uSm + WS_OFF + kc*CH,  uWl = uWh + 2*CH;
#pragma unroll
            for (int ks = 0; ks < 4; ks++) {
                int k = ks * 16;
                u32 aH[4], aL[4], bH[4][2], bL[4][2];
                ldsm4(aH[0], aH[1], aH[2], aH[3], uGh + (u32)((arow2*SAS + k + acolo)*2));
                ldsm4(aL[0], aL[1], aL[2], aL[3], uGl + (u32)((arow2*SAS + k + acolo)*2));
#pragma unroll
                for (int pr = 0; pr < 2; pr++) {
                    u32 off = (u32)(((brow2 + pr*16)*SAS + k + bcolo)*2);
                    ldsm4(bH[2*pr][0], bH[2*pr][1], bH[2*pr+1][0], bH[2*pr+1][1], uWh + off);
                    ldsm4(bL[2*pr][0], bL[2*pr][1], bL[2*pr+1][0], bL[2*pr+1][1], uWl + off);
                }
#pragma unroll
                for (int nt = 0; nt < 4; nt++) {
                    mma_bf16(oacc[nt], aH, bH[nt]);
                    mma_bf16(oacc[nt], aH, bL[nt]);
                    mma_bf16(oacc[nt], aL, bH[nt]);
                }
            }
        }
        __syncthreads();
    }

    float* O0 = Out + (grow + wm2*16 + r)*E_;
    float* O1 = O0 + 8*(size_t)E_;
#pragma unroll
    for (int nt = 0; nt < 4; nt++) {
        int ge = wn2*32 + nt*8 + c2_;
        float2 o0, o1;
        o0.x = oacc[nt][0]; o0.y = oacc[nt][1];
        o1.x = oacc[nt][2]; o1.y = oacc[nt][3];
        *(float2*)&O0[ge] = o0;
        *(float2*)&O1[ge] = o1;
    }
}

// ---------------- launch ----------------
extern "C" void kernel_launch(void* const* d_in, const int* in_sizes, int n_in,
                              void* d_out, int out_size)
{
    const float* pu     = (const float*)d_in[0];  // [B,H,Nt,P]
    const float* pb     = (const float*)d_in[1];  // [B,H,Nt,1]
    const float* mu     = (const float*)d_in[2];  // [B,Nl,P]
    const float* logvar = (const float*)d_in[3];  // [B,Nl,P]
    const float* pi     = (const float*)d_in[4];  // [B,Nl,1]
    const float* wv     = (const float*)d_in[5];  // [H,E,P]
    const float* bvv    = (const float*)d_in[6];  // [H,E,Nl]
    const unsigned char* mask = (const unsigned char*)d_in[7]; // [B*H,1,Nl]

    float* out  = (float*)d_out;                  // [BH,Nt,E]
    float* attn = out + (size_t)BH*NT*E_;         // [BH,Nt,Nl]

    __nv_bfloat16 *Uh, *Ul, *Wh, *Wl;
    cudaGetSymbolAddress((void**)&Uh, g_Uh);
    cudaGetSymbolAddress((void**)&Ul, g_Ul);
    cudaGetSymbolAddress((void**)&Wh, g_Wh);
    cudaGetSymbolAddress((void**)&Wl, g_Wl);

    const int SM_SCORES = 3 * 4 * TILE_B;         // 221184 B (3-stage)
    cudaFuncSetAttribute(k_scores_D, cudaFuncAttributeMaxDynamicSharedMemorySize, SM_SCORES);
    cudaFuncSetAttribute(k_av_out,   cudaFuncAttributeMaxDynamicSharedMemorySize, SM_FUSED);

    k_prep    <<<dim3(NL, B_),    256>>>(mu, logvar, pi, mask);
    k_split   <<<32768,           256>>>(pu, Uh, Ul);
    k_split   <<<1024,            256>>>(wv, Wh, Wl);
    k_scores_D<<<dim3(5, 64, B_), 256, SM_SCORES>>>(pb, attn, bvv);
    k_softmax <<<BH*NT,           128>>>(attn);
    k_av_out  <<<dim3(8, BH),     256, SM_FUSED>>>(pu, out);
}